// round 14
// baseline (speedup 1.0000x reference)
#include <cuda_runtime.h>
#include <cuda_fp16.h>
#include <cstdint>
#include <math.h>

#define BB 8
#define CC 512
#define PP 4096
#define NHH 8

// ---- scratch (static device globals; no allocation) ----
__device__ float g_box1[BB*64*PP];
__device__ float g_boxes[BB*4*PP];
__device__ float g_edge1[BB*64*PP];
__device__ float g_edge[BB*NHH*PP];
__device__ __half g_qkvh[(size_t)BB*1536*PP];   // fp16 qkv (identical numerics for attn)
__device__ float g_attn[(size_t)BB*NHH*64*64*64];
__device__ float g_agg[(size_t)BB*CC*PP];
__device__ __half g_yh[(size_t)BB*CC*PP];       // fp16 pre-BN fusion output
__device__ float g_gnstats[BB*8*2];
__device__ float g_bnstats[CC*2];
__device__ __half g_xhi[(size_t)BB*PP*1024];    // [b][p][ci]
__device__ __half g_wfhi[512*9*1024];           // [co][tap][ci]
__device__ __half g_wbhi[64*9*512];
__device__ __half g_wqhi[1536*512];

__device__ __forceinline__ float geluf(float x) {
    return 0.5f * x * (1.0f + erff(x * 0.70710678118654752440f));
}
__device__ __forceinline__ float sigm(float x) { return 1.0f / (1.0f + __expf(-x)); }

// ---- arch-neutral tensor-core helpers (sm_80+ PTX only) ----
__device__ __forceinline__ uint32_t smem_u32(const void* p) {
    uint32_t a;
    asm("{ .reg .u64 t; cvta.to.shared.u64 t, %1; cvt.u32.u64 %0, t; }" : "=r"(a) : "l"(p));
    return a;
}
__device__ __forceinline__ void ldsm_x4(uint32_t* r, uint32_t addr) {
    asm volatile("ldmatrix.sync.aligned.m8n8.x4.shared.b16 {%0,%1,%2,%3}, [%4];"
        : "=r"(r[0]), "=r"(r[1]), "=r"(r[2]), "=r"(r[3]) : "r"(addr));
}
__device__ __forceinline__ void mma16816(float* d, const uint32_t* a, const uint32_t* b) {
    asm volatile("mma.sync.aligned.m16n8k16.row.col.f32.f16.f16.f32 "
        "{%0,%1,%2,%3}, {%4,%5,%6,%7}, {%8,%9}, {%0,%1,%2,%3};"
        : "+f"(d[0]), "+f"(d[1]), "+f"(d[2]), "+f"(d[3])
        : "r"(a[0]), "r"(a[1]), "r"(a[2]), "r"(a[3]), "r"(b[0]), "r"(b[1]));
}
__device__ __forceinline__ void cpa16(uint32_t dst, const void* src, uint32_t sz) {
    asm volatile("cp.async.cg.shared.global [%0], [%1], 16, %2;\n" :: "r"(dst), "l"(src), "r"(sz));
}
#define CP_COMMIT() asm volatile("cp.async.commit_group;\n" ::: "memory")
#define CP_WAIT1()  asm volatile("cp.async.wait_group 1;\n" ::: "memory")
#define CP_WAIT0()  asm volatile("cp.async.wait_group 0;\n" ::: "memory")

// ---- convert / transpose: NCHW fp32 -> [b][p][ci] fp16 ----
__global__ void split_k(const float* __restrict__ src, __half* __restrict__ xhi,
                        int Cn, int cibase)
{
    __shared__ float tile[32][33];
    int bz = blockIdx.z, c0 = blockIdx.x * 32, p0 = blockIdx.y * 32;
    int tx = threadIdx.x, ty = threadIdx.y;
#pragma unroll
    for (int i = 0; i < 32; i += 8)
        tile[ty + i][tx] = src[((size_t)bz * Cn + c0 + ty + i) * 4096 + p0 + tx];
    __syncthreads();
#pragma unroll
    for (int i = 0; i < 32; i += 8) {
        size_t o = ((size_t)bz * 4096 + p0 + ty + i) * 1024 + cibase + c0 + tx;
        xhi[o] = __float2half_rn(tile[tx][ty + i]);
    }
}

// OIHW fp32 -> [co][tap][ci] fp16
__global__ void wsplit_k(const float* __restrict__ w, __half* __restrict__ whi,
                         int Cin, int taps, size_t total)
{
    size_t i = (size_t)blockIdx.x * 256 + threadIdx.x;
    if (i >= total) return;
    int tap = (int)(i % taps);
    size_t t2 = i / taps;
    int ci = (int)(t2 % Cin);
    int co = (int)(t2 / Cin);
    whi[((size_t)co * taps + tap) * Cin + ci] = __float2half_rn(w[i]);
}

// ================= fusion conv3x3 (1024->512): B-halo reuse, fp16 out ==========
#define FA_ST 18432
#define FB0   36864
#define FB_ST 38016
#define FUS_SMEM 112896

__device__ __forceinline__ void fus_loadA(uint32_t sb, int t,
    const __half* __restrict__ whi, int co0, int c)
{
    int cik = c / 9, tap = c - cik * 9, ci0 = cik * 64;
#pragma unroll
    for (int i = 0; i < 4; i++) {
        int idx = t + i * 256;
        int row = idx >> 3, seg = idx & 7;
        const __half* src = whi + ((size_t)(co0 + row) * 9 + tap) * 1024 + ci0 + seg * 8;
        cpa16(sb + row * 144 + seg * 16, src, 16u);
    }
}

__device__ __forceinline__ void fus_loadB(uint32_t sb, int t,
    const __half* __restrict__ xhi, int b, int h0, int cik)
{
    int ci0 = cik * 64;
    for (int idx = t; idx < 2112; idx += 256) {
        int row = idx >> 3, seg = idx & 7;
        int hrel = row / 66, wrel = row - hrel * 66;
        int h = h0 - 1 + hrel, w = wrel - 1;
        bool ok = ((unsigned)h < 64u) && ((unsigned)w < 64u);
        const __half* src = xhi
            + ((size_t)(b * 4096 + (ok ? h * 64 + w : 0))) * 1024 + ci0 + seg * 8;
        cpa16(sb + row * 144 + seg * 16, src, ok ? 16u : 0u);
    }
}

__global__ __launch_bounds__(256, 2) void fus_mm(
    const __half* __restrict__ whi, const __half* __restrict__ xhi,
    const float* __restrict__ bias, __half* __restrict__ out)
{
    extern __shared__ char dynsmem[];
    const int b = blockIdx.x >> 5;
    const int pbase = (blockIdx.x & 31) * 128;
    const int h0 = pbase >> 6;
    const int co0 = blockIdx.y * 128;
    const int t = threadIdx.x, lane = t & 31, warp = t >> 5;
    const int wm = warp & 1, wn = warp >> 1;
    const uint32_t sb = smem_u32(dynsmem);

    float acc[4][4][4];
#pragma unroll
    for (int fm = 0; fm < 4; fm++)
#pragma unroll
        for (int fn = 0; fn < 4; fn++)
#pragma unroll
            for (int k = 0; k < 4; k++) acc[fm][fn][k] = 0.f;

    fus_loadB(sb + FB0, t, xhi, b, h0, 0);
    fus_loadA(sb, t, whi, co0, 0);
    CP_COMMIT();
    fus_loadA(sb + FA_ST, t, whi, co0, 1);
    CP_COMMIT();

    const int arow = wm * 64 + (lane & 15);
    const int akoff = (lane >> 4) * 16;
    const int l8 = lane & 7, grp = lane >> 3;
    const int bprel = wn * 32 + l8 + (grp >> 1) * 8;
    const int bkoff = (grp & 1) * 16;
    const int bhw = (bprel >> 6) * 66 + (bprel & 63);

    for (int c = 0; c < 144; c++) {
        if (c == 143) { CP_WAIT0(); } else { CP_WAIT1(); }
        __syncthreads();
        const int cik = c / 9, tap = c - cik * 9;
        const int tapoff = (tap / 3) * 66 + (tap % 3);
        const uint32_t Ast = sb + (c & 1) * FA_ST;
        const uint32_t Bst = sb + FB0 + (cik & 1) * FB_ST;
        const uint32_t abase = Ast + arow * 144 + akoff;
        const uint32_t bbase = Bst + (bhw + tapoff) * 144 + bkoff;
#pragma unroll
        for (int ks = 0; ks < 4; ks++) {
            const int kb = ks * 32;
            uint32_t ah[4][4];
#pragma unroll
            for (int fm = 0; fm < 4; fm++)
                ldsm_x4(ah[fm], abase + fm * 16 * 144 + kb);
            uint32_t bh[4][2];
#pragma unroll
            for (int fp = 0; fp < 2; fp++) {
                uint32_t r[4];
                ldsm_x4(r, bbase + fp * 16 * 144 + kb);
                bh[fp*2][0] = r[0]; bh[fp*2][1] = r[1];
                bh[fp*2+1][0] = r[2]; bh[fp*2+1][1] = r[3];
            }
#pragma unroll
            for (int fm = 0; fm < 4; fm++)
#pragma unroll
                for (int fn = 0; fn < 4; fn++)
                    mma16816(acc[fm][fn], ah[fm], bh[fn]);
        }
        __syncthreads();
        if (c + 2 < 144)
            fus_loadA(Ast, t, whi, co0, c + 2);
        if (tap == 0 && cik + 1 < 16)
            fus_loadB(sb + FB0 + ((cik + 1) & 1) * FB_ST, t, xhi, b, h0, cik + 1);
        CP_COMMIT();
    }

    const int r0 = lane >> 2, c0 = (lane & 3) * 2;
#pragma unroll
    for (int fm = 0; fm < 4; fm++) {
        int co = co0 + wm * 64 + fm * 16 + r0;
        float bv0 = bias[co], bv8 = bias[co + 8];
        __half* op0 = out + ((size_t)b * 512 + co) * 4096 + pbase;
        __half* op8 = op0 + (size_t)8 * 4096;
#pragma unroll
        for (int fn = 0; fn < 4; fn++) {
            int p = wn * 32 + fn * 8 + c0;
            *(__half2*)(op0 + p) = __floats2half2_rn(acc[fm][fn][0] + bv0, acc[fm][fn][1] + bv0);
            *(__half2*)(op8 + p) = __floats2half2_rn(acc[fm][fn][2] + bv8, acc[fm][fn][3] + bv8);
        }
    }
}

// ---- generic mma.sync implicit GEMM (qkv 1x1, box conv), 1-term fp16 ----
// OH: 1 = fp16 output, 0 = fp32 output
template<int TAPS, int COUTV, int ROWSA, int ROWSB>
__device__ __forceinline__ void mm_load(uint32_t sb, int t,
    const __half* __restrict__ whi, const __half* __restrict__ xhi,
    int co0, int WCin, int b, int pbase, int c)
{
    const int B_HI_ = ROWSA * 144;
    int cik = c / TAPS, tap = c - cik * TAPS;
    int dh = (TAPS == 9) ? tap / 3 - 1 : 0;
    int dw = (TAPS == 9) ? tap % 3 - 1 : 0;
    int ci0 = cik * 64;
#pragma unroll
    for (int i = 0; i < ROWSA / 32; i++) {
        int idx = t + i * 256;
        int row = idx >> 3, seg = idx & 7;
        int rr = (COUTV < ROWSA && row >= COUTV) ? 0 : row;
        const __half* src = whi
            + ((size_t)(co0 + rr) * TAPS + tap) * WCin + ci0 + seg * 8;
        cpa16(sb + row * 144 + seg * 16, src,
              (COUTV < ROWSA && row >= COUTV) ? 0u : 16u);
    }
#pragma unroll
    for (int i = 0; i < ROWSB / 32; i++) {
        int idx = t + i * 256;
        int row = idx >> 3, seg = idx & 7;
        int p = pbase + row;
        int ih = (p >> 6) + dh, iw = (p & 63) + dw;
        bool ok = (TAPS == 1) || (((unsigned)ih < 64u) && ((unsigned)iw < 64u));
        const __half* src = xhi
            + ((size_t)(b * 4096 + (ok ? ih * 64 + iw : 0))) * 1024 + ci0 + seg * 8;
        cpa16(sb + B_HI_ + row * 144 + seg * 16, src, ok ? 16u : 0u);
    }
}

template<int TAPS, int ACT, int COUTV, int ROWSA, int ROWSB, int OH>
__global__ __launch_bounds__(256, 2) void mma_mm(
    const __half* __restrict__ whi, const __half* __restrict__ xhi,
    const float* __restrict__ bias, void* __restrict__ outv, int WCin, int Cout)
{
    extern __shared__ char dynsmem[];
    const int B_HI_ = ROWSA * 144;
    const int MSTAGE_ = (ROWSA + ROWSB) * 144;
    const int NPT = 4096 / ROWSB;
    const int b = blockIdx.x / NPT;
    const int pbase = (blockIdx.x % NPT) * ROWSB;
    const int co0 = blockIdx.y * ROWSA;
    const int t = threadIdx.x, lane = t & 31, warp = t >> 5;
    const int wm = (ROWSA == 128) ? (warp & 1) : 0;
    const int wn = (ROWSA == 128) ? (warp >> 1) : warp;
    const uint32_t sb0 = smem_u32(dynsmem);
    const int NCH = (WCin / 64) * TAPS;

    float acc[4][4][4];
#pragma unroll
    for (int fm = 0; fm < 4; fm++)
#pragma unroll
        for (int fn = 0; fn < 4; fn++)
#pragma unroll
            for (int k = 0; k < 4; k++) acc[fm][fn][k] = 0.f;

    mm_load<TAPS, COUTV, ROWSA, ROWSB>(sb0, t, whi, xhi, co0, WCin, b, pbase, 0); CP_COMMIT();
    mm_load<TAPS, COUTV, ROWSA, ROWSB>(sb0 + MSTAGE_, t, whi, xhi, co0, WCin, b, pbase, 1); CP_COMMIT();

    const int arow = wm * 64 + (lane & 15);
    const int akoff = (lane >> 4) * 16;
    const int l8 = lane & 7, grp = lane >> 3;
    const int brow = wn * 32 + l8 + (grp >> 1) * 8;
    const int bkoff = (grp & 1) * 16;

    for (int c = 0; c < NCH; c++) {
        const uint32_t sb = sb0 + (c & 1) * MSTAGE_;
        if (c == NCH - 1) { CP_WAIT0(); } else { CP_WAIT1(); }
        __syncthreads();
        const uint32_t abase = sb + arow * 144 + akoff;
        const uint32_t bbase = sb + B_HI_ + brow * 144 + bkoff;
#pragma unroll
        for (int ks = 0; ks < 4; ks++) {
            const int kb = ks * 32;
            uint32_t ah[4][4];
#pragma unroll
            for (int fm = 0; fm < 4; fm++)
                ldsm_x4(ah[fm], abase + fm * 16 * 144 + kb);
            uint32_t bh[4][2];
#pragma unroll
            for (int fp = 0; fp < 2; fp++) {
                uint32_t r[4];
                ldsm_x4(r, bbase + fp * 16 * 144 + kb);
                bh[fp*2][0] = r[0]; bh[fp*2][1] = r[1];
                bh[fp*2+1][0] = r[2]; bh[fp*2+1][1] = r[3];
            }
#pragma unroll
            for (int fm = 0; fm < 4; fm++)
#pragma unroll
                for (int fn = 0; fn < 4; fn++)
                    mma16816(acc[fm][fn], ah[fm], bh[fn]);
        }
        __syncthreads();
        if (c + 2 < NCH) {
            mm_load<TAPS, COUTV, ROWSA, ROWSB>(sb, t, whi, xhi, co0, WCin, b, pbase, c + 2);
            CP_COMMIT();
        }
    }

    const int r0 = lane >> 2, c0 = (lane & 3) * 2;
#pragma unroll
    for (int fm = 0; fm < 4; fm++) {
        int co = co0 + wm * 64 + fm * 16 + r0;
        bool v0ok = (COUTV >= ROWSA) || (co < COUTV);
        bool v8ok = (COUTV >= ROWSA) || (co + 8 < COUTV);
        float bv0 = v0ok ? bias[co] : 0.f;
        float bv8 = v8ok ? bias[co + 8] : 0.f;
#pragma unroll
        for (int fn = 0; fn < 4; fn++) {
            int p = wn * 32 + fn * 8 + c0;
            float a0 = acc[fm][fn][0] + bv0, a1 = acc[fm][fn][1] + bv0;
            float a2 = acc[fm][fn][2] + bv8, a3 = acc[fm][fn][3] + bv8;
            if (ACT == 1) { a0 = geluf(a0); a1 = geluf(a1); a2 = geluf(a2); a3 = geluf(a3); }
            if (OH) {
                __half* op0 = (__half*)outv + ((size_t)b * Cout + co) * 4096 + pbase;
                __half* op8 = op0 + (size_t)8 * 4096;
                if (v0ok) *(__half2*)(op0 + p) = __floats2half2_rn(a0, a1);
                if (v8ok) *(__half2*)(op8 + p) = __floats2half2_rn(a2, a3);
            } else {
                float* op0 = (float*)outv + ((size_t)b * Cout + co) * 4096 + pbase;
                float* op8 = op0 + (size_t)8 * 4096;
                if (v0ok) *(float2*)(op0 + p) = make_float2(a0, a1);
                if (v8ok) *(float2*)(op8 + p) = make_float2(a2, a3);
            }
        }
    }
}

// ---- attention QK logits via mma (fp16 inputs) ----
__global__ __launch_bounds__(128) void attn_qk_mma(
    const __half* __restrict__ qkv, const float* __restrict__ edge, float* __restrict__ attn)
{
    int id = blockIdx.x;
    int i = id & 63, h = (id >> 6) & 7, b = id >> 9;
    const __half* Q = qkv + ((size_t)(b * 1536 + h * 64 + i)) * PP;
    const __half* K = qkv + ((size_t)(b * 1536 + 512 + h * 64 + i)) * PP;
    __shared__ __half sQh[64*72], sKh[64*72];
    int t = threadIdx.x, lane = t & 31, warp = t >> 5;
    int wm = warp & 1, wn = warp >> 1;
    for (int idx = t; idx < 4096; idx += 128) {
        int y = idx >> 6, c = idx & 63;
        sQh[c*72 + y] = Q[idx];
        sKh[c*72 + y] = K[idx];
    }
    __syncthreads();
    float acc[2][4][4];
#pragma unroll
    for (int fm = 0; fm < 2; fm++)
#pragma unroll
        for (int fn = 0; fn < 4; fn++)
#pragma unroll
            for (int k = 0; k < 4; k++) acc[fm][fn][k] = 0.f;

    const uint32_t aQh = smem_u32(sQh), aKh = smem_u32(sKh);
    const int arow = wm * 32 + (lane & 15), akoff = (lane >> 4) * 16;
    const int l8 = lane & 7, grp = lane >> 3;
    const int brow = wn * 32 + l8 + (grp >> 1) * 8, bkoff = (grp & 1) * 16;
#pragma unroll
    for (int ks = 0; ks < 4; ks++) {
        const int kb = ks * 32;
        uint32_t ah[2][4];
#pragma unroll
        for (int fm = 0; fm < 2; fm++)
            ldsm_x4(ah[fm], aQh + (arow + fm*16) * 144 + akoff + kb);
        uint32_t bh[4][2];
#pragma unroll
        for (int fp = 0; fp < 2; fp++) {
            uint32_t r[4];
            ldsm_x4(r, aKh + (brow + fp*16) * 144 + bkoff + kb);
            bh[fp*2][0] = r[0]; bh[fp*2][1] = r[1];
            bh[fp*2+1][0] = r[2]; bh[fp*2+1][1] = r[3];
        }
#pragma unroll
        for (int fm = 0; fm < 2; fm++)
#pragma unroll
            for (int fn = 0; fn < 4; fn++)
                mma16816(acc[fm][fn], ah[fm], bh[fn]);
    }
    const int r0 = lane >> 2, c0 = (lane & 3) * 2;
    float* op = attn + (size_t)id * 4096;
    const float* ep = edge + (size_t)id * 64;
#pragma unroll
    for (int fm = 0; fm < 2; fm++) {
        int w0 = wm * 32 + fm * 16 + r0;
        float e0 = ep[w0], e8 = ep[w0 + 8];
#pragma unroll
        for (int fn = 0; fn < 4; fn++) {
            int Wp = wn * 32 + fn * 8 + c0;
            op[w0*64 + Wp]       = acc[fm][fn][0] * 0.125f + e0;
            op[w0*64 + Wp + 1]   = acc[fm][fn][1] * 0.125f + e0;
            op[(w0+8)*64 + Wp]   = acc[fm][fn][2] * 0.125f + e8;
            op[(w0+8)*64 + Wp+1] = acc[fm][fn][3] * 0.125f + e8;
        }
    }
}

// ---- attention AV via mma (fp16 V, fp32 probs converted) ----
__global__ __launch_bounds__(128) void attn_av_mma(
    const __half* __restrict__ qkv, const float* __restrict__ attn, float* __restrict__ agg)
{
    int id = blockIdx.x;
    int i = id & 63, h = (id >> 6) & 7, b = id >> 9;
    const __half* V = qkv + ((size_t)(b * 1536 + 1024 + h * 64 + i)) * PP;
    const float* A = attn + (size_t)id * 4096;
    __shared__ __half sVh[64*72], sAh[64*72];
    int t = threadIdx.x, lane = t & 31, warp = t >> 5;
    int wm = warp & 1, wn = warp >> 1;
    for (int idx = t; idx < 4096; idx += 128) {
        int r = idx >> 6, c = idx & 63;
        sVh[r*72 + c] = V[idx];
        sAh[r*72 + c] = __float2half_rn(A[idx]);
    }
    __syncthreads();
    float acc[2][4][4];
#pragma unroll
    for (int fm = 0; fm < 2; fm++)
#pragma unroll
        for (int fn = 0; fn < 4; fn++)
#pragma unroll
            for (int k = 0; k < 4; k++) acc[fm][fn][k] = 0.f;

    const uint32_t aVh = smem_u32(sVh), aAh = smem_u32(sAh);
    const int arow = wm * 32 + (lane & 15), akoff = (lane >> 4) * 16;
    const int l8 = lane & 7, grp = lane >> 3;
    const int brow = wn * 32 + l8 + (grp >> 1) * 8, bkoff = (grp & 1) * 16;
#pragma unroll
    for (int ks = 0; ks < 4; ks++) {
        const int kb = ks * 32;
        uint32_t ah[2][4];
#pragma unroll
        for (int fm = 0; fm < 2; fm++)
            ldsm_x4(ah[fm], aVh + (arow + fm*16) * 144 + akoff + kb);
        uint32_t bh[4][2];
#pragma unroll
        for (int fp = 0; fp < 2; fp++) {
            uint32_t r[4];
            ldsm_x4(r, aAh + (brow + fp*16) * 144 + bkoff + kb);
            bh[fp*2][0] = r[0]; bh[fp*2][1] = r[1];
            bh[fp*2+1][0] = r[2]; bh[fp*2+1][1] = r[3];
        }
#pragma unroll
        for (int fm = 0; fm < 2; fm++)
#pragma unroll
            for (int fn = 0; fn < 4; fn++)
                mma16816(acc[fm][fn], ah[fm], bh[fn]);
    }
    const int r0 = lane >> 2, c0 = (lane & 3) * 2;
    float* op = agg + ((size_t)(b * 512 + h * 64 + i)) * PP;
#pragma unroll
    for (int fm = 0; fm < 2; fm++) {
        int d0 = wm * 32 + fm * 16 + r0;
#pragma unroll
        for (int fn = 0; fn < 4; fn++) {
            int w = wn * 32 + fn * 8 + c0;
            op[d0*64 + w]       = acc[fm][fn][0];
            op[d0*64 + w + 1]   = acc[fm][fn][1];
            op[(d0+8)*64 + w]   = acc[fm][fn][2];
            op[(d0+8)*64 + w+1] = acc[fm][fn][3];
        }
    }
}

// ---- FFMA 3x3 conv (edge net: Cin=4 -> 64 only) ----
#define CI_CHUNK 8
template<int ACT>
__global__ __launch_bounds__(128) void conv3x3_k(
    const float* __restrict__ in1, int Cin,
    const float* __restrict__ wgt, const float* __restrict__ bias,
    float* __restrict__ out, int Cout)
{
    const int bh = blockIdx.x, b = bh >> 6, h = bh & 63;
    const int co0 = blockIdx.y * 64;
    const int t = threadIdx.x, tx = t & 7, ty = t >> 3;
    __shared__ float sIn[CI_CHUNK][3][66];
    __shared__ float sW[64][CI_CHUNK * 9];
    float acc[4][8];
#pragma unroll
    for (int a = 0; a < 4; a++)
#pragma unroll
        for (int j = 0; j < 8; j++) acc[a][j] = 0.f;

    for (int cb = 0; cb < Cin; cb += CI_CHUNK) {
        __syncthreads();
        for (int idx = t; idx < CI_CHUNK * 3 * 66; idx += 128) {
            int ci = idx / 198, rem = idx - ci * 198, r = rem / 66, col = rem - r * 66;
            int cg = cb + ci;
            float v = 0.f;
            int gh = h - 1 + r, gw = col - 1;
            if (cg < Cin && (unsigned)gh < 64u && (unsigned)gw < 64u)
                v = in1[((size_t)(b * Cin + cg)) * PP + gh * 64 + gw];
            sIn[ci][r][col] = v;
        }
        for (int idx = t; idx < 64 * CI_CHUNK * 9; idx += 128) {
            int co = idx / (CI_CHUNK * 9), rem = idx - co * (CI_CHUNK * 9);
            int ci = rem / 9, kk = rem - ci * 9, cg = cb + ci;
            sW[co][ci * 9 + kk] = (cg < Cin) ? wgt[((size_t)(co0 + co) * Cin + cg) * 9 + kk] : 0.f;
        }
        __syncthreads();
#pragma unroll 2
        for (int ci = 0; ci < CI_CHUNK; ci++) {
#pragma unroll
            for (int r = 0; r < 3; r++) {
                float iv[10];
#pragma unroll
                for (int j = 0; j < 10; j++) iv[j] = sIn[ci][r][tx * 8 + j];
#pragma unroll
                for (int cj = 0; cj < 4; cj++) {
                    float w0 = sW[ty * 4 + cj][ci * 9 + r * 3 + 0];
                    float w1 = sW[ty * 4 + cj][ci * 9 + r * 3 + 1];
                    float w2 = sW[ty * 4 + cj][ci * 9 + r * 3 + 2];
#pragma unroll
                    for (int wj = 0; wj < 8; wj++) {
                        acc[cj][wj] = fmaf(w0, iv[wj + 0], acc[cj][wj]);
                        acc[cj][wj] = fmaf(w1, iv[wj + 1], acc[cj][wj]);
                        acc[cj][wj] = fmaf(w2, iv[wj + 2], acc[cj][wj]);
                    }
                }
            }
        }
    }
#pragma unroll
    for (int cj = 0; cj < 4; cj++) {
        int co = co0 + ty * 4 + cj;
        float bv = bias[co];
#pragma unroll
        for (int wj = 0; wj < 8; wj++) {
            float v = acc[cj][wj] + bv;
            if (ACT == 1) v = geluf(v);
            out[(((size_t)b * Cout + co) * 64 + h) * 64 + tx * 8 + wj] = v;
        }
    }
}

template<int ACT>
__global__ void conv1x1_small_k(const float* __restrict__ in, const float* __restrict__ wgt,
                                const float* __restrict__ bias, float* __restrict__ out,
                                int Cin, int Cout)
{
    int bc = blockIdx.x, b = bc / Cout, co = bc - b * Cout;
    int p = blockIdx.y * 256 + threadIdx.x;
    float acc = bias[co];
    const float* ip = in + (size_t)b * Cin * PP + p;
    const float* wp = wgt + (size_t)co * Cin;
    for (int ci = 0; ci < Cin; ci++)
        acc = fmaf(wp[ci], ip[(size_t)ci * PP], acc);
    if (ACT == 2) acc = sigm(acc);
    out[((size_t)b * Cout + co) * PP + p] = acc;
}

// ---- GroupNorm stats ----
__global__ void gn_stats_k(const float* __restrict__ x, float* __restrict__ stats)
{
    int bg = blockIdx.x, b = bg >> 3, g = bg & 7;
    const float* p = x + ((size_t)b * 64 + g * 8) * PP;
    float s = 0.f, s2 = 0.f;
    for (int i = threadIdx.x; i < 8 * PP; i += 256) {
        float v = p[i]; s += v; s2 += v * v;
    }
    __shared__ float rs[8], rs2[8];
#pragma unroll
    for (int o = 16; o > 0; o >>= 1) {
        s += __shfl_down_sync(0xffffffffu, s, o);
        s2 += __shfl_down_sync(0xffffffffu, s2, o);
    }
    int w = threadIdx.x >> 5, l = threadIdx.x & 31;
    if (l == 0) { rs[w] = s; rs2[w] = s2; }
    __syncthreads();
    if (w == 0) {
        s = (l < 8) ? rs[l] : 0.f; s2 = (l < 8) ? rs2[l] : 0.f;
#pragma unroll
        for (int o = 4; o > 0; o >>= 1) {
            s += __shfl_down_sync(0xffffffffu, s, o);
            s2 += __shfl_down_sync(0xffffffffu, s2, o);
        }
        if (l == 0) {
            float m = s / 32768.f;
            stats[bg * 2] = m;
            stats[bg * 2 + 1] = s2 / 32768.f - m * m;
        }
    }
}

// ---- fused GN + GELU + 1x1 conv (64->8): edge net tail ----
__global__ __launch_bounds__(256) void edge2_k(
    const float* __restrict__ edge1, const float* __restrict__ stats,
    const float* __restrict__ gamma, const float* __restrict__ beta,
    const float* __restrict__ w2, const float* __restrict__ b2,
    float* __restrict__ edge)
{
    int b = blockIdx.x;
    int p = blockIdx.y * 256 + threadIdx.x;
    __shared__ float sm[8], srs[8], sg[64], sbt[64], sw[8][64], sb2[8];
    int t = threadIdx.x;
    if (t < 8) {
        sm[t] = stats[(b * 8 + t) * 2];
        srs[t] = rsqrtf(stats[(b * 8 + t) * 2 + 1] + 1e-5f);
        sb2[t] = b2[t];
    }
    if (t < 64) { sg[t] = gamma[t]; sbt[t] = beta[t]; }
    for (int i = t; i < 512; i += 256) sw[i >> 6][i & 63] = w2[i];
    __syncthreads();

    float acc[8];
#pragma unroll
    for (int co = 0; co < 8; co++) acc[co] = sb2[co];
    const float* ip = edge1 + (size_t)b * 64 * PP + p;
    for (int ci = 0; ci < 64; ci++) {
        int g = ci >> 3;
        float xn = geluf((ip[(size_t)ci * PP] - sm[g]) * srs[g] * sg[ci] + sbt[ci]);
#pragma unroll
        for (int co = 0; co < 8; co++)
            acc[co] = fmaf(sw[co][ci], xn, acc[co]);
    }
#pragma unroll
    for (int co = 0; co < 8; co++)
        edge[((size_t)b * 8 + co) * PP + p] = acc[co];
}

// ---- softmax over i ----
__global__ __launch_bounds__(128) void softmax_i_k(float* __restrict__ attn)
{
    int n = blockIdx.x * 128 + threadIdx.x;
    int bh = n >> 12, ww = n & 4095;
    float* p = attn + (size_t)bh * 262144 + ww;
    float x[64], mx = -1e30f;
#pragma unroll
    for (int i = 0; i < 64; i++) { x[i] = p[(size_t)i * 4096]; mx = fmaxf(mx, x[i]); }
    float s = 0.f;
#pragma unroll
    for (int i = 0; i < 64; i++) { x[i] = __expf(x[i] - mx); s += x[i]; }
    float inv = 1.f / s;
#pragma unroll
    for (int i = 0; i < 64; i++) p[(size_t)i * 4096] = x[i] * inv;
}

// ---- BatchNorm (fp16 y) ----
__global__ void bn_stats_k(const __half* __restrict__ y, float* __restrict__ stats)
{
    int c = blockIdx.x;
    float s = 0.f, s2 = 0.f;
    for (int n = threadIdx.x; n < 32768; n += 256) {
        int b = n >> 12, p = n & 4095;
        float v = __half2float(y[((size_t)b * CC + c) * PP + p]);
        s += v; s2 += v * v;
    }
    __shared__ float rs[8], rs2[8];
#pragma unroll
    for (int o = 16; o > 0; o >>= 1) {
        s += __shfl_down_sync(0xffffffffu, s, o);
        s2 += __shfl_down_sync(0xffffffffu, s2, o);
    }
    int w = threadIdx.x >> 5, l = threadIdx.x & 31;
    if (l == 0) { rs[w] = s; rs2[w] = s2; }
    __syncthreads();
    if (w == 0) {
        s = (l < 8) ? rs[l] : 0.f; s2 = (l < 8) ? rs2[l] : 0.f;
#pragma unroll
        for (int o = 4; o > 0; o >>= 1) {
            s += __shfl_down_sync(0xffffffffu, s, o);
            s2 += __shfl_down_sync(0xffffffffu, s2, o);
        }
        if (l == 0) {
            float m = s / 32768.f;
            stats[c * 2] = m;
            stats[c * 2 + 1] = s2 / 32768.f - m * m;
        }
    }
}

__global__ void bn_apply_k(const __half* __restrict__ y, const float* __restrict__ stats,
                           const float* __restrict__ g, const float* __restrict__ bt,
                           float* __restrict__ out)
{
    size_t idx = (size_t)blockIdx.x * 256 + threadIdx.x;
    int c = (int)((idx >> 12) & 511);
    float m = stats[c * 2], v = stats[c * 2 + 1];
    float yn = (__half2float(y[idx]) - m) * rsqrtf(v + 1e-5f) * g[c] + bt[c];
    out[idx] = yn * (1.f / (1.f + __expf(-yn)));
}

// ---- launch ----
extern "C" void kernel_launch(void* const* d_in, const int* in_sizes, int n_in,
                              void* d_out, int out_size)
{
    const float* x       = (const float*)d_in[0];
    const float* box_w1  = (const float*)d_in[1];
    const float* box_b1  = (const float*)d_in[2];
    const float* box_w2  = (const float*)d_in[3];
    const float* box_b2  = (const float*)d_in[4];
    const float* edge_w1 = (const float*)d_in[5];
    const float* edge_b1 = (const float*)d_in[6];
    const float* gn_g    = (const float*)d_in[7];
    const float* gn_b    = (const float*)d_in[8];
    const float* edge_w2 = (const float*)d_in[9];
    const float* edge_b2 = (const float*)d_in[10];
    const float* qkv_w   = (const float*)d_in[11];
    const float* qkv_b   = (const float*)d_in[12];
    const float* fus_w   = (const float*)d_in[13];
    const float* fus_b   = (const float*)d_in[14];
    const float* bn_g    = (const float*)d_in[15];
    const float* bn_b    = (const float*)d_in[16];
    float* out = (float*)d_out;

    float *box1, *boxes, *edge1, *edge, *attn, *agg, *gnst, *bnst;
    __half *qkvh, *yh, *xhi, *wfhi, *wbhi, *wqhi;
    cudaGetSymbolAddress((void**)&box1,  g_box1);
    cudaGetSymbolAddress((void**)&boxes, g_boxes);
    cudaGetSymbolAddress((void**)&edge1, g_edge1);
    cudaGetSymbolAddress((void**)&edge,  g_edge);
    cudaGetSymbolAddress((void**)&qkvh,  g_qkvh);
    cudaGetSymbolAddress((void**)&attn,  g_attn);
    cudaGetSymbolAddress((void**)&agg,   g_agg);
    cudaGetSymbolAddress((void**)&yh,    g_yh);
    cudaGetSymbolAddress((void**)&gnst,  g_gnstats);
    cudaGetSymbolAddress((void**)&bnst,  g_bnstats);
    cudaGetSymbolAddress((void**)&xhi,   g_xhi);
    cudaGetSymbolAddress((void**)&wfhi,  g_wfhi);
    cudaGetSymbolAddress((void**)&wbhi,  g_wbhi);
    cudaGetSymbolAddress((void**)&wqhi,  g_wqhi);

    cudaFuncSetAttribute((const void*)mma_mm<1, 0, 128, 128, 128, 1>, cudaFuncAttributeMaxDynamicSharedMemorySize, 2 * (128 + 128) * 144);
    cudaFuncSetAttribute((const void*)mma_mm<9, 1, 64, 64, 256, 0>,   cudaFuncAttributeMaxDynamicSharedMemorySize, 2 * (64 + 256) * 144);
    cudaFuncSetAttribute((const void*)fus_mm, cudaFuncAttributeMaxDynamicSharedMemorySize, FUS_SMEM);

    // preprocessing (fp16 conversions)
    split_k<<<dim3(16, 128, 8), dim3(32, 8)>>>(x, xhi, 512, 0);
    wsplit_k<<<(512 * 1024 * 9 + 255) / 256, 256>>>(fus_w, wfhi, 1024, 9, (size_t)512 * 1024 * 9);
    wsplit_k<<<(64 * 512 * 9 + 255) / 256, 256>>>(box_w1, wbhi, 512, 9, (size_t)64 * 512 * 9);
    wsplit_k<<<(1536 * 512 + 255) / 256, 256>>>(qkv_w, wqhi, 512, 1, (size_t)1536 * 512);

    // box conv3x3(512->64)+GELU (fp32 out)
    mma_mm<9, 1, 64, 64, 256, 0><<<dim3(128, 1), 256, 2 * (64 + 256) * 144>>>(
        wbhi, xhi, box_b1, box1, 512, 64);

    // qkv 1x1 (512->1536) -> fp16 out (numerically identical for attention)
    mma_mm<1, 0, 128, 128, 128, 1><<<dim3(256, 12), 256, 2 * (128 + 128) * 144>>>(
        wqhi, xhi, qkv_b, qkvh, 512, 1536);

    // box tail + edge net (GN stats, then fused GN+GELU+1x1)
    conv1x1_small_k<2><<<dim3(32, 16), 256>>>(box1, box_w2, box_b2, boxes, 64, 4);
    conv3x3_k<0><<<dim3(512, 1), 128>>>(boxes, 4, edge_w1, edge_b1, edge1, 64);
    gn_stats_k<<<64, 256>>>(edge1, gnst);
    edge2_k<<<dim3(8, 16), 256>>>(edge1, gnst, gn_g, gn_b, edge_w2, edge_b2, edge);

    // attention (tensor cores, fp16 qkv)
    attn_qk_mma<<<4096, 128>>>(qkvh, edge, attn);
    softmax_i_k<<<2048, 128>>>(attn);
    attn_av_mma<<<4096, 128>>>(qkvh, attn, agg);

    // convert agg into ci[512:1024) of the fp16 buffer
    split_k<<<dim3(16, 128, 8), dim3(32, 8)>>>(agg, xhi, 512, 512);

    // fusion conv3x3 (1024->512) -> fp16 y
    fus_mm<<<dim3(256, 4), 256, FUS_SMEM>>>(wfhi, xhi, fus_b, yh);

    // batchnorm + SiLU (fp16 y)
    bn_stats_k<<<512, 256>>>(yh, bnst);
    bn_apply_k<<<65536, 256>>>(yh, bnst, bn_g, bn_b, out);
}

// round 15
// speedup vs baseline: 1.4937x; 1.4937x over previous
#include <cuda_runtime.h>
#include <cuda_fp16.h>
#include <cstdint>
#include <math.h>

#define BB 8
#define CC 512
#define PP 4096
#define NHH 8

// ---- scratch (static device globals; no allocation) ----
__device__ float g_box1[BB*64*PP];
__device__ float g_boxes[BB*4*PP];
__device__ float g_edge1[BB*64*PP];
__device__ float g_edge[BB*NHH*PP];
__device__ float g_qkv[(size_t)BB*1536*PP];
__device__ float g_attn[(size_t)BB*NHH*64*64*64];
__device__ float g_agg[(size_t)BB*CC*PP];
__device__ float g_y[(size_t)BB*CC*PP];
__device__ float g_gnstats[BB*8*2];
__device__ float g_bnstats[CC*2];
__device__ __half g_xhi[(size_t)BB*PP*1024];   // [b][p][ci]
__device__ __half g_wfhi[512*9*1024];          // [co][tap][ci]
__device__ __half g_wbhi[64*9*512];
__device__ __half g_wqhi[1536*512];

__device__ __forceinline__ float geluf(float x) {
    return 0.5f * x * (1.0f + erff(x * 0.70710678118654752440f));
}
__device__ __forceinline__ float sigm(float x) { return 1.0f / (1.0f + __expf(-x)); }

// ---- arch-neutral tensor-core helpers (sm_80+ PTX only) ----
__device__ __forceinline__ uint32_t smem_u32(const void* p) {
    uint32_t a;
    asm("{ .reg .u64 t; cvta.to.shared.u64 t, %1; cvt.u32.u64 %0, t; }" : "=r"(a) : "l"(p));
    return a;
}
__device__ __forceinline__ void ldsm_x4(uint32_t* r, uint32_t addr) {
    asm volatile("ldmatrix.sync.aligned.m8n8.x4.shared.b16 {%0,%1,%2,%3}, [%4];"
        : "=r"(r[0]), "=r"(r[1]), "=r"(r[2]), "=r"(r[3]) : "r"(addr));
}
__device__ __forceinline__ void mma16816(float* d, const uint32_t* a, const uint32_t* b) {
    asm volatile("mma.sync.aligned.m16n8k16.row.col.f32.f16.f16.f32 "
        "{%0,%1,%2,%3}, {%4,%5,%6,%7}, {%8,%9}, {%0,%1,%2,%3};"
        : "+f"(d[0]), "+f"(d[1]), "+f"(d[2]), "+f"(d[3])
        : "r"(a[0]), "r"(a[1]), "r"(a[2]), "r"(a[3]), "r"(b[0]), "r"(b[1]));
}
__device__ __forceinline__ void cpa16(uint32_t dst, const void* src, uint32_t sz) {
    asm volatile("cp.async.cg.shared.global [%0], [%1], 16, %2;\n" :: "r"(dst), "l"(src), "r"(sz));
}
#define CP_COMMIT() asm volatile("cp.async.commit_group;\n" ::: "memory")
#define CP_WAIT1()  asm volatile("cp.async.wait_group 1;\n" ::: "memory")
#define CP_WAIT0()  asm volatile("cp.async.wait_group 0;\n" ::: "memory")

// ---- convert / transpose: NCHW fp32 -> [b][p][ci] fp16 ----
__global__ void split_k(const float* __restrict__ src, __half* __restrict__ xhi,
                        int Cn, int cibase)
{
    __shared__ float tile[32][33];
    int bz = blockIdx.z, c0 = blockIdx.x * 32, p0 = blockIdx.y * 32;
    int tx = threadIdx.x, ty = threadIdx.y;
#pragma unroll
    for (int i = 0; i < 32; i += 8)
        tile[ty + i][tx] = src[((size_t)bz * Cn + c0 + ty + i) * 4096 + p0 + tx];
    __syncthreads();
#pragma unroll
    for (int i = 0; i < 32; i += 8) {
        size_t o = ((size_t)bz * 4096 + p0 + ty + i) * 1024 + cibase + c0 + tx;
        xhi[o] = __float2half_rn(tile[tx][ty + i]);
    }
}

// OIHW fp32 -> [co][tap][ci] fp16
__global__ void wsplit_k(const float* __restrict__ w, __half* __restrict__ whi,
                         int Cin, int taps, size_t total)
{
    size_t i = (size_t)blockIdx.x * 256 + threadIdx.x;
    if (i >= total) return;
    int tap = (int)(i % taps);
    size_t t2 = i / taps;
    int ci = (int)(t2 % Cin);
    int co = (int)(t2 / Cin);
    whi[((size_t)co * taps + tap) * Cin + ci] = __float2half_rn(w[i]);
}

// ================= fusion conv3x3 (1024->512): B-halo reuse + 1-term fp16 ==========
#define FA_ST 18432
#define FB0   36864
#define FB_ST 38016
#define FUS_SMEM 112896

__device__ __forceinline__ void fus_loadA(uint32_t sb, int t,
    const __half* __restrict__ whi, int co0, int c)
{
    int cik = c / 9, tap = c - cik * 9, ci0 = cik * 64;
#pragma unroll
    for (int i = 0; i < 4; i++) {
        int idx = t + i * 256;
        int row = idx >> 3, seg = idx & 7;
        const __half* src = whi + ((size_t)(co0 + row) * 9 + tap) * 1024 + ci0 + seg * 8;
        cpa16(sb + row * 144 + seg * 16, src, 16u);
    }
}

__device__ __forceinline__ void fus_loadB(uint32_t sb, int t,
    const __half* __restrict__ xhi, int b, int h0, int cik)
{
    int ci0 = cik * 64;
    for (int idx = t; idx < 2112; idx += 256) {
        int row = idx >> 3, seg = idx & 7;
        int hrel = row / 66, wrel = row - hrel * 66;
        int h = h0 - 1 + hrel, w = wrel - 1;
        bool ok = ((unsigned)h < 64u) && ((unsigned)w < 64u);
        const __half* src = xhi
            + ((size_t)(b * 4096 + (ok ? h * 64 + w : 0))) * 1024 + ci0 + seg * 8;
        cpa16(sb + row * 144 + seg * 16, src, ok ? 16u : 0u);
    }
}

__global__ __launch_bounds__(256, 2) void fus_mm(
    const __half* __restrict__ whi, const __half* __restrict__ xhi,
    const float* __restrict__ bias, float* __restrict__ out)
{
    extern __shared__ char dynsmem[];
    const int b = blockIdx.x >> 5;
    const int pbase = (blockIdx.x & 31) * 128;
    const int h0 = pbase >> 6;
    const int co0 = blockIdx.y * 128;
    const int t = threadIdx.x, lane = t & 31, warp = t >> 5;
    const int wm = warp & 1, wn = warp >> 1;
    const uint32_t sb = smem_u32(dynsmem);

    float acc[4][4][4];
#pragma unroll
    for (int fm = 0; fm < 4; fm++)
#pragma unroll
        for (int fn = 0; fn < 4; fn++)
#pragma unroll
            for (int k = 0; k < 4; k++) acc[fm][fn][k] = 0.f;

    fus_loadB(sb + FB0, t, xhi, b, h0, 0);
    fus_loadA(sb, t, whi, co0, 0);
    CP_COMMIT();
    fus_loadA(sb + FA_ST, t, whi, co0, 1);
    CP_COMMIT();

    const int arow = wm * 64 + (lane & 15);
    const int akoff = (lane >> 4) * 16;
    const int l8 = lane & 7, grp = lane >> 3;
    const int bprel = wn * 32 + l8 + (grp >> 1) * 8;
    const int bkoff = (grp & 1) * 16;
    const int bhw = (bprel >> 6) * 66 + (bprel & 63);

    for (int c = 0; c < 144; c++) {
        if (c == 143) { CP_WAIT0(); } else { CP_WAIT1(); }
        __syncthreads();
        const int cik = c / 9, tap = c - cik * 9;
        const int tapoff = (tap / 3) * 66 + (tap % 3);
        const uint32_t Ast = sb + (c & 1) * FA_ST;
        const uint32_t Bst = sb + FB0 + (cik & 1) * FB_ST;
        const uint32_t abase = Ast + arow * 144 + akoff;
        const uint32_t bbase = Bst + (bhw + tapoff) * 144 + bkoff;
#pragma unroll
        for (int ks = 0; ks < 4; ks++) {
            const int kb = ks * 32;
            uint32_t ah[4][4];
#pragma unroll
            for (int fm = 0; fm < 4; fm++)
                ldsm_x4(ah[fm], abase + fm * 16 * 144 + kb);
            uint32_t bh[4][2];
#pragma unroll
            for (int fp = 0; fp < 2; fp++) {
                uint32_t r[4];
                ldsm_x4(r, bbase + fp * 16 * 144 + kb);
                bh[fp*2][0] = r[0]; bh[fp*2][1] = r[1];
                bh[fp*2+1][0] = r[2]; bh[fp*2+1][1] = r[3];
            }
#pragma unroll
            for (int fm = 0; fm < 4; fm++)
#pragma unroll
                for (int fn = 0; fn < 4; fn++)
                    mma16816(acc[fm][fn], ah[fm], bh[fn]);
        }
        __syncthreads();
        if (c + 2 < 144)
            fus_loadA(Ast, t, whi, co0, c + 2);
        if (tap == 0 && cik + 1 < 16)
            fus_loadB(sb + FB0 + ((cik + 1) & 1) * FB_ST, t, xhi, b, h0, cik + 1);
        CP_COMMIT();
    }

    const int r0 = lane >> 2, c0 = (lane & 3) * 2;
#pragma unroll
    for (int fm = 0; fm < 4; fm++) {
        int co = co0 + wm * 64 + fm * 16 + r0;
        float bv0 = bias[co], bv8 = bias[co + 8];
        float* op0 = out + ((size_t)b * 512 + co) * 4096 + pbase;
        float* op8 = op0 + (size_t)8 * 4096;
#pragma unroll
        for (int fn = 0; fn < 4; fn++) {
            int p = wn * 32 + fn * 8 + c0;
            *(float2*)(op0 + p) = make_float2(acc[fm][fn][0] + bv0, acc[fm][fn][1] + bv0);
            *(float2*)(op8 + p) = make_float2(acc[fm][fn][2] + bv8, acc[fm][fn][3] + bv8);
        }
    }
}

// ---- generic mma.sync implicit GEMM (qkv 1x1, box conv), 1-term fp16 ----
template<int TAPS, int COUTV, int ROWSA, int ROWSB>
__device__ __forceinline__ void mm_load(uint32_t sb, int t,
    const __half* __restrict__ whi, const __half* __restrict__ xhi,
    int co0, int WCin, int b, int pbase, int c)
{
    const int B_HI_ = ROWSA * 144;
    int cik = c / TAPS, tap = c - cik * TAPS;
    int dh = (TAPS == 9) ? tap / 3 - 1 : 0;
    int dw = (TAPS == 9) ? tap % 3 - 1 : 0;
    int ci0 = cik * 64;
#pragma unroll
    for (int i = 0; i < ROWSA / 32; i++) {
        int idx = t + i * 256;
        int row = idx >> 3, seg = idx & 7;
        int rr = (COUTV < ROWSA && row >= COUTV) ? 0 : row;
        const __half* src = whi
            + ((size_t)(co0 + rr) * TAPS + tap) * WCin + ci0 + seg * 8;
        cpa16(sb + row * 144 + seg * 16, src,
              (COUTV < ROWSA && row >= COUTV) ? 0u : 16u);
    }
#pragma unroll
    for (int i = 0; i < ROWSB / 32; i++) {
        int idx = t + i * 256;
        int row = idx >> 3, seg = idx & 7;
        int p = pbase + row;
        int ih = (p >> 6) + dh, iw = (p & 63) + dw;
        bool ok = (TAPS == 1) || (((unsigned)ih < 64u) && ((unsigned)iw < 64u));
        const __half* src = xhi
            + ((size_t)(b * 4096 + (ok ? ih * 64 + iw : 0))) * 1024 + ci0 + seg * 8;
        cpa16(sb + B_HI_ + row * 144 + seg * 16, src, ok ? 16u : 0u);
    }
}

template<int TAPS, int ACT, int COUTV, int ROWSA, int ROWSB>
__global__ __launch_bounds__(256, 2) void mma_mm(
    const __half* __restrict__ whi, const __half* __restrict__ xhi,
    const float* __restrict__ bias, float* __restrict__ out, int WCin, int Cout)
{
    extern __shared__ char dynsmem[];
    const int B_HI_ = ROWSA * 144;
    const int MSTAGE_ = (ROWSA + ROWSB) * 144;
    const int NPT = 4096 / ROWSB;
    const int b = blockIdx.x / NPT;
    const int pbase = (blockIdx.x % NPT) * ROWSB;
    const int co0 = blockIdx.y * ROWSA;
    const int t = threadIdx.x, lane = t & 31, warp = t >> 5;
    const int wm = (ROWSA == 128) ? (warp & 1) : 0;
    const int wn = (ROWSA == 128) ? (warp >> 1) : warp;
    const uint32_t sb0 = smem_u32(dynsmem);
    const int NCH = (WCin / 64) * TAPS;

    float acc[4][4][4];
#pragma unroll
    for (int fm = 0; fm < 4; fm++)
#pragma unroll
        for (int fn = 0; fn < 4; fn++)
#pragma unroll
            for (int k = 0; k < 4; k++) acc[fm][fn][k] = 0.f;

    mm_load<TAPS, COUTV, ROWSA, ROWSB>(sb0, t, whi, xhi, co0, WCin, b, pbase, 0); CP_COMMIT();
    mm_load<TAPS, COUTV, ROWSA, ROWSB>(sb0 + MSTAGE_, t, whi, xhi, co0, WCin, b, pbase, 1); CP_COMMIT();

    const int arow = wm * 64 + (lane & 15);
    const int akoff = (lane >> 4) * 16;
    const int l8 = lane & 7, grp = lane >> 3;
    const int brow = wn * 32 + l8 + (grp >> 1) * 8;
    const int bkoff = (grp & 1) * 16;

    for (int c = 0; c < NCH; c++) {
        const uint32_t sb = sb0 + (c & 1) * MSTAGE_;
        if (c == NCH - 1) { CP_WAIT0(); } else { CP_WAIT1(); }
        __syncthreads();
        const uint32_t abase = sb + arow * 144 + akoff;
        const uint32_t bbase = sb + B_HI_ + brow * 144 + bkoff;
#pragma unroll
        for (int ks = 0; ks < 4; ks++) {
            const int kb = ks * 32;
            uint32_t ah[4][4];
#pragma unroll
            for (int fm = 0; fm < 4; fm++)
                ldsm_x4(ah[fm], abase + fm * 16 * 144 + kb);
            uint32_t bh[4][2];
#pragma unroll
            for (int fp = 0; fp < 2; fp++) {
                uint32_t r[4];
                ldsm_x4(r, bbase + fp * 16 * 144 + kb);
                bh[fp*2][0] = r[0]; bh[fp*2][1] = r[1];
                bh[fp*2+1][0] = r[2]; bh[fp*2+1][1] = r[3];
            }
#pragma unroll
            for (int fm = 0; fm < 4; fm++)
#pragma unroll
                for (int fn = 0; fn < 4; fn++)
                    mma16816(acc[fm][fn], ah[fm], bh[fn]);
        }
        __syncthreads();
        if (c + 2 < NCH) {
            mm_load<TAPS, COUTV, ROWSA, ROWSB>(sb, t, whi, xhi, co0, WCin, b, pbase, c + 2);
            CP_COMMIT();
        }
    }

    const int r0 = lane >> 2, c0 = (lane & 3) * 2;
#pragma unroll
    for (int fm = 0; fm < 4; fm++) {
        int co = co0 + wm * 64 + fm * 16 + r0;
        bool v0ok = (COUTV >= ROWSA) || (co < COUTV);
        bool v8ok = (COUTV >= ROWSA) || (co + 8 < COUTV);
        float bv0 = v0ok ? bias[co] : 0.f;
        float bv8 = v8ok ? bias[co + 8] : 0.f;
        float* op0 = out + ((size_t)b * Cout + co) * 4096 + pbase;
        float* op8 = op0 + (size_t)8 * 4096;
#pragma unroll
        for (int fn = 0; fn < 4; fn++) {
            int p = wn * 32 + fn * 8 + c0;
            float a0 = acc[fm][fn][0] + bv0, a1 = acc[fm][fn][1] + bv0;
            float a2 = acc[fm][fn][2] + bv8, a3 = acc[fm][fn][3] + bv8;
            if (ACT == 1) { a0 = geluf(a0); a1 = geluf(a1); a2 = geluf(a2); a3 = geluf(a3); }
            if (v0ok) *(float2*)(op0 + p) = make_float2(a0, a1);
            if (v8ok) *(float2*)(op8 + p) = make_float2(a2, a3);
        }
    }
}

// ---- attention QK logits via mma (1-term fp16) ----
__global__ __launch_bounds__(128) void attn_qk_mma(
    const float* __restrict__ qkv, const float* __restrict__ edge, float* __restrict__ attn)
{
    int id = blockIdx.x;
    int i = id & 63, h = (id >> 6) & 7, b = id >> 9;
    const float* Q = qkv + ((size_t)(b * 1536 + h * 64 + i)) * PP;
    const float* K = qkv + ((size_t)(b * 1536 + 512 + h * 64 + i)) * PP;
    __shared__ __half sQh[64*72], sKh[64*72];
    int t = threadIdx.x, lane = t & 31, warp = t >> 5;
    int wm = warp & 1, wn = warp >> 1;
    for (int idx = t; idx < 4096; idx += 128) {
        int y = idx >> 6, c = idx & 63;
        sQh[c*72 + y] = __float2half_rn(Q[idx]);
        sKh[c*72 + y] = __float2half_rn(K[idx]);
    }
    __syncthreads();
    float acc[2][4][4];
#pragma unroll
    for (int fm = 0; fm < 2; fm++)
#pragma unroll
        for (int fn = 0; fn < 4; fn++)
#pragma unroll
            for (int k = 0; k < 4; k++) acc[fm][fn][k] = 0.f;

    const uint32_t aQh = smem_u32(sQh), aKh = smem_u32(sKh);
    const int arow = wm * 32 + (lane & 15), akoff = (lane >> 4) * 16;
    const int l8 = lane & 7, grp = lane >> 3;
    const int brow = wn * 32 + l8 + (grp >> 1) * 8, bkoff = (grp & 1) * 16;
#pragma unroll
    for (int ks = 0; ks < 4; ks++) {
        const int kb = ks * 32;
        uint32_t ah[2][4];
#pragma unroll
        for (int fm = 0; fm < 2; fm++)
            ldsm_x4(ah[fm], aQh + (arow + fm*16) * 144 + akoff + kb);
        uint32_t bh[4][2];
#pragma unroll
        for (int fp = 0; fp < 2; fp++) {
            uint32_t r[4];
            ldsm_x4(r, aKh + (brow + fp*16) * 144 + bkoff + kb);
            bh[fp*2][0] = r[0]; bh[fp*2][1] = r[1];
            bh[fp*2+1][0] = r[2]; bh[fp*2+1][1] = r[3];
        }
#pragma unroll
        for (int fm = 0; fm < 2; fm++)
#pragma unroll
            for (int fn = 0; fn < 4; fn++)
                mma16816(acc[fm][fn], ah[fm], bh[fn]);
    }
    const int r0 = lane >> 2, c0 = (lane & 3) * 2;
    float* op = attn + (size_t)id * 4096;
    const float* ep = edge + (size_t)id * 64;
#pragma unroll
    for (int fm = 0; fm < 2; fm++) {
        int w0 = wm * 32 + fm * 16 + r0;
        float e0 = ep[w0], e8 = ep[w0 + 8];
#pragma unroll
        for (int fn = 0; fn < 4; fn++) {
            int Wp = wn * 32 + fn * 8 + c0;
            op[w0*64 + Wp]       = acc[fm][fn][0] * 0.125f + e0;
            op[w0*64 + Wp + 1]   = acc[fm][fn][1] * 0.125f + e0;
            op[(w0+8)*64 + Wp]   = acc[fm][fn][2] * 0.125f + e8;
            op[(w0+8)*64 + Wp+1] = acc[fm][fn][3] * 0.125f + e8;
        }
    }
}

// ---- attention AV via mma (1-term fp16) ----
__global__ __launch_bounds__(128) void attn_av_mma(
    const float* __restrict__ qkv, const float* __restrict__ attn, float* __restrict__ agg)
{
    int id = blockIdx.x;
    int i = id & 63, h = (id >> 6) & 7, b = id >> 9;
    const float* V = qkv + ((size_t)(b * 1536 + 1024 + h * 64 + i)) * PP;
    const float* A = attn + (size_t)id * 4096;
    __shared__ __half sVh[64*72], sAh[64*72];
    int t = threadIdx.x, lane = t & 31, warp = t >> 5;
    int wm = warp & 1, wn = warp >> 1;
    for (int idx = t; idx < 4096; idx += 128) {
        int r = idx >> 6, c = idx & 63;
        sVh[r*72 + c] = __float2half_rn(V[idx]);
        sAh[r*72 + c] = __float2half_rn(A[idx]);
    }
    __syncthreads();
    float acc[2][4][4];
#pragma unroll
    for (int fm = 0; fm < 2; fm++)
#pragma unroll
        for (int fn = 0; fn < 4; fn++)
#pragma unroll
            for (int k = 0; k < 4; k++) acc[fm][fn][k] = 0.f;

    const uint32_t aVh = smem_u32(sVh), aAh = smem_u32(sAh);
    const int arow = wm * 32 + (lane & 15), akoff = (lane >> 4) * 16;
    const int l8 = lane & 7, grp = lane >> 3;
    const int brow = wn * 32 + l8 + (grp >> 1) * 8, bkoff = (grp & 1) * 16;
#pragma unroll
    for (int ks = 0; ks < 4; ks++) {
        const int kb = ks * 32;
        uint32_t ah[2][4];
#pragma unroll
        for (int fm = 0; fm < 2; fm++)
            ldsm_x4(ah[fm], aVh + (arow + fm*16) * 144 + akoff + kb);
        uint32_t bh[4][2];
#pragma unroll
        for (int fp = 0; fp < 2; fp++) {
            uint32_t r[4];
            ldsm_x4(r, aAh + (brow + fp*16) * 144 + bkoff + kb);
            bh[fp*2][0] = r[0]; bh[fp*2][1] = r[1];
            bh[fp*2+1][0] = r[2]; bh[fp*2+1][1] = r[3];
        }
#pragma unroll
        for (int fm = 0; fm < 2; fm++)
#pragma unroll
            for (int fn = 0; fn < 4; fn++)
                mma16816(acc[fm][fn], ah[fm], bh[fn]);
    }
    const int r0 = lane >> 2, c0 = (lane & 3) * 2;
    float* op = agg + ((size_t)(b * 512 + h * 64 + i)) * PP;
#pragma unroll
    for (int fm = 0; fm < 2; fm++) {
        int d0 = wm * 32 + fm * 16 + r0;
#pragma unroll
        for (int fn = 0; fn < 4; fn++) {
            int w = wn * 32 + fn * 8 + c0;
            op[d0*64 + w]       = acc[fm][fn][0];
            op[d0*64 + w + 1]   = acc[fm][fn][1];
            op[(d0+8)*64 + w]   = acc[fm][fn][2];
            op[(d0+8)*64 + w+1] = acc[fm][fn][3];
        }
    }
}

// ---- FFMA 3x3 conv (edge net: Cin=4 -> 64 only) ----
#define CI_CHUNK 8
template<int ACT>
__global__ __launch_bounds__(128) void conv3x3_k(
    const float* __restrict__ in1, int Cin,
    const float* __restrict__ wgt, const float* __restrict__ bias,
    float* __restrict__ out, int Cout)
{
    const int bh = blockIdx.x, b = bh >> 6, h = bh & 63;
    const int co0 = blockIdx.y * 64;
    const int t = threadIdx.x, tx = t & 7, ty = t >> 3;
    __shared__ float sIn[CI_CHUNK][3][66];
    __shared__ float sW[64][CI_CHUNK * 9];
    float acc[4][8];
#pragma unroll
    for (int a = 0; a < 4; a++)
#pragma unroll
        for (int j = 0; j < 8; j++) acc[a][j] = 0.f;

    for (int cb = 0; cb < Cin; cb += CI_CHUNK) {
        __syncthreads();
        for (int idx = t; idx < CI_CHUNK * 3 * 66; idx += 128) {
            int ci = idx / 198, rem = idx - ci * 198, r = rem / 66, col = rem - r * 66;
            int cg = cb + ci;
            float v = 0.f;
            int gh = h - 1 + r, gw = col - 1;
            if (cg < Cin && (unsigned)gh < 64u && (unsigned)gw < 64u)
                v = in1[((size_t)(b * Cin + cg)) * PP + gh * 64 + gw];
            sIn[ci][r][col] = v;
        }
        for (int idx = t; idx < 64 * CI_CHUNK * 9; idx += 128) {
            int co = idx / (CI_CHUNK * 9), rem = idx - co * (CI_CHUNK * 9);
            int ci = rem / 9, kk = rem - ci * 9, cg = cb + ci;
            sW[co][ci * 9 + kk] = (cg < Cin) ? wgt[((size_t)(co0 + co) * Cin + cg) * 9 + kk] : 0.f;
        }
        __syncthreads();
#pragma unroll 2
        for (int ci = 0; ci < CI_CHUNK; ci++) {
#pragma unroll
            for (int r = 0; r < 3; r++) {
                float iv[10];
#pragma unroll
                for (int j = 0; j < 10; j++) iv[j] = sIn[ci][r][tx * 8 + j];
#pragma unroll
                for (int cj = 0; cj < 4; cj++) {
                    float w0 = sW[ty * 4 + cj][ci * 9 + r * 3 + 0];
                    float w1 = sW[ty * 4 + cj][ci * 9 + r * 3 + 1];
                    float w2 = sW[ty * 4 + cj][ci * 9 + r * 3 + 2];
#pragma unroll
                    for (int wj = 0; wj < 8; wj++) {
                        acc[cj][wj] = fmaf(w0, iv[wj + 0], acc[cj][wj]);
                        acc[cj][wj] = fmaf(w1, iv[wj + 1], acc[cj][wj]);
                        acc[cj][wj] = fmaf(w2, iv[wj + 2], acc[cj][wj]);
                    }
                }
            }
        }
    }
#pragma unroll
    for (int cj = 0; cj < 4; cj++) {
        int co = co0 + ty * 4 + cj;
        float bv = bias[co];
#pragma unroll
        for (int wj = 0; wj < 8; wj++) {
            float v = acc[cj][wj] + bv;
            if (ACT == 1) v = geluf(v);
            out[(((size_t)b * Cout + co) * 64 + h) * 64 + tx * 8 + wj] = v;
        }
    }
}

template<int ACT>
__global__ void conv1x1_small_k(const float* __restrict__ in, const float* __restrict__ wgt,
                                const float* __restrict__ bias, float* __restrict__ out,
                                int Cin, int Cout)
{
    int bc = blockIdx.x, b = bc / Cout, co = bc - b * Cout;
    int p = blockIdx.y * 256 + threadIdx.x;
    float acc = bias[co];
    const float* ip = in + (size_t)b * Cin * PP + p;
    const float* wp = wgt + (size_t)co * Cin;
    for (int ci = 0; ci < Cin; ci++)
        acc = fmaf(wp[ci], ip[(size_t)ci * PP], acc);
    if (ACT == 2) acc = sigm(acc);
    out[((size_t)b * Cout + co) * PP + p] = acc;
}

// ---- GroupNorm stats ----
__global__ void gn_stats_k(const float* __restrict__ x, float* __restrict__ stats)
{
    int bg = blockIdx.x, b = bg >> 3, g = bg & 7;
    const float* p = x + ((size_t)b * 64 + g * 8) * PP;
    float s = 0.f, s2 = 0.f;
    for (int i = threadIdx.x; i < 8 * PP; i += 256) {
        float v = p[i]; s += v; s2 += v * v;
    }
    __shared__ float rs[8], rs2[8];
#pragma unroll
    for (int o = 16; o > 0; o >>= 1) {
        s += __shfl_down_sync(0xffffffffu, s, o);
        s2 += __shfl_down_sync(0xffffffffu, s2, o);
    }
    int w = threadIdx.x >> 5, l = threadIdx.x & 31;
    if (l == 0) { rs[w] = s; rs2[w] = s2; }
    __syncthreads();
    if (w == 0) {
        s = (l < 8) ? rs[l] : 0.f; s2 = (l < 8) ? rs2[l] : 0.f;
#pragma unroll
        for (int o = 4; o > 0; o >>= 1) {
            s += __shfl_down_sync(0xffffffffu, s, o);
            s2 += __shfl_down_sync(0xffffffffu, s2, o);
        }
        if (l == 0) {
            float m = s / 32768.f;
            stats[bg * 2] = m;
            stats[bg * 2 + 1] = s2 / 32768.f - m * m;
        }
    }
}

// ---- fused GN + GELU + 1x1 conv (64->8): edge net tail ----
__global__ __launch_bounds__(256) void edge2_k(
    const float* __restrict__ edge1, const float* __restrict__ stats,
    const float* __restrict__ gamma, const float* __restrict__ beta,
    const float* __restrict__ w2, const float* __restrict__ b2,
    float* __restrict__ edge)
{
    int b = blockIdx.x;
    int p = blockIdx.y * 256 + threadIdx.x;
    __shared__ float sm[8], srs[8], sg[64], sbt[64], sw[8][64], sb2[8];
    int t = threadIdx.x;
    if (t < 8) {
        sm[t] = stats[(b * 8 + t) * 2];
        srs[t] = rsqrtf(stats[(b * 8 + t) * 2 + 1] + 1e-5f);
        sb2[t] = b2[t];
    }
    if (t < 64) { sg[t] = gamma[t]; sbt[t] = beta[t]; }
    for (int i = t; i < 512; i += 256) sw[i >> 6][i & 63] = w2[i];
    __syncthreads();

    float acc[8];
#pragma unroll
    for (int co = 0; co < 8; co++) acc[co] = sb2[co];
    const float* ip = edge1 + (size_t)b * 64 * PP + p;
    for (int ci = 0; ci < 64; ci++) {
        int g = ci >> 3;
        float xn = geluf((ip[(size_t)ci * PP] - sm[g]) * srs[g] * sg[ci] + sbt[ci]);
#pragma unroll
        for (int co = 0; co < 8; co++)
            acc[co] = fmaf(sw[co][ci], xn, acc[co]);
    }
#pragma unroll
    for (int co = 0; co < 8; co++)
        edge[((size_t)b * 8 + co) * PP + p] = acc[co];
}

// ---- softmax over i ----
__global__ __launch_bounds__(128) void softmax_i_k(float* __restrict__ attn)
{
    int n = blockIdx.x * 128 + threadIdx.x;
    int bh = n >> 12, ww = n & 4095;
    float* p = attn + (size_t)bh * 262144 + ww;
    float x[64], mx = -1e30f;
#pragma unroll
    for (int i = 0; i < 64; i++) { x[i] = p[(size_t)i * 4096]; mx = fmaxf(mx, x[i]); }
    float s = 0.f;
#pragma unroll
    for (int i = 0; i < 64; i++) { x[i] = __expf(x[i] - mx); s += x[i]; }
    float inv = 1.f / s;
#pragma unroll
    for (int i = 0; i < 64; i++) p[(size_t)i * 4096] = x[i] * inv;
}

// ---- BatchNorm ----
__global__ void bn_stats_k(const float* __restrict__ y, float* __restrict__ stats)
{
    int c = blockIdx.x;
    float s = 0.f, s2 = 0.f;
    for (int n = threadIdx.x; n < 32768; n += 256) {
        int b = n >> 12, p = n & 4095;
        float v = y[((size_t)b * CC + c) * PP + p];
        s += v; s2 += v * v;
    }
    __shared__ float rs[8], rs2[8];
#pragma unroll
    for (int o = 16; o > 0; o >>= 1) {
        s += __shfl_down_sync(0xffffffffu, s, o);
        s2 += __shfl_down_sync(0xffffffffu, s2, o);
    }
    int w = threadIdx.x >> 5, l = threadIdx.x & 31;
    if (l == 0) { rs[w] = s; rs2[w] = s2; }
    __syncthreads();
    if (w == 0) {
        s = (l < 8) ? rs[l] : 0.f; s2 = (l < 8) ? rs2[l] : 0.f;
#pragma unroll
        for (int o = 4; o > 0; o >>= 1) {
            s += __shfl_down_sync(0xffffffffu, s, o);
            s2 += __shfl_down_sync(0xffffffffu, s2, o);
        }
        if (l == 0) {
            float m = s / 32768.f;
            stats[c * 2] = m;
            stats[c * 2 + 1] = s2 / 32768.f - m * m;
        }
    }
}

__global__ void bn_apply_k(const float* __restrict__ y, const float* __restrict__ stats,
                           const float* __restrict__ g, const float* __restrict__ bt,
                           float* __restrict__ out)
{
    size_t idx = (size_t)blockIdx.x * 256 + threadIdx.x;
    int c = (int)((idx >> 12) & 511);
    float m = stats[c * 2], v = stats[c * 2 + 1];
    float yn = (y[idx] - m) * rsqrtf(v + 1e-5f) * g[c] + bt[c];
    out[idx] = yn * (1.f / (1.f + __expf(-yn)));
}

// ---- launch ----
extern "C" void kernel_launch(void* const* d_in, const int* in_sizes, int n_in,
                              void* d_out, int out_size)
{
    const float* x       = (const float*)d_in[0];
    const float* box_w1  = (const float*)d_in[1];
    const float* box_b1  = (const float*)d_in[2];
    const float* box_w2  = (const float*)d_in[3];
    const float* box_b2  = (const float*)d_in[4];
    const float* edge_w1 = (const float*)d_in[5];
    const float* edge_b1 = (const float*)d_in[6];
    const float* gn_g    = (const float*)d_in[7];
    const float* gn_b    = (const float*)d_in[8];
    const float* edge_w2 = (const float*)d_in[9];
    const float* edge_b2 = (const float*)d_in[10];
    const float* qkv_w   = (const float*)d_in[11];
    const float* qkv_b   = (const float*)d_in[12];
    const float* fus_w   = (const float*)d_in[13];
    const float* fus_b   = (const float*)d_in[14];
    const float* bn_g    = (const float*)d_in[15];
    const float* bn_b    = (const float*)d_in[16];
    float* out = (float*)d_out;

    float *box1, *boxes, *edge1, *edge, *qkv, *attn, *agg, *y, *gnst, *bnst;
    __half *xhi, *wfhi, *wbhi, *wqhi;
    cudaGetSymbolAddress((void**)&box1,  g_box1);
    cudaGetSymbolAddress((void**)&boxes, g_boxes);
    cudaGetSymbolAddress((void**)&edge1, g_edge1);
    cudaGetSymbolAddress((void**)&edge,  g_edge);
    cudaGetSymbolAddress((void**)&qkv,   g_qkv);
    cudaGetSymbolAddress((void**)&attn,  g_attn);
    cudaGetSymbolAddress((void**)&agg,   g_agg);
    cudaGetSymbolAddress((void**)&y,     g_y);
    cudaGetSymbolAddress((void**)&gnst,  g_gnstats);
    cudaGetSymbolAddress((void**)&bnst,  g_bnstats);
    cudaGetSymbolAddress((void**)&xhi,   g_xhi);
    cudaGetSymbolAddress((void**)&wfhi,  g_wfhi);
    cudaGetSymbolAddress((void**)&wbhi,  g_wbhi);
    cudaGetSymbolAddress((void**)&wqhi,  g_wqhi);

    cudaFuncSetAttribute((const void*)mma_mm<1, 0, 128, 128, 128>, cudaFuncAttributeMaxDynamicSharedMemorySize, 2 * (128 + 128) * 144);
    cudaFuncSetAttribute((const void*)mma_mm<9, 1, 64, 64, 256>,   cudaFuncAttributeMaxDynamicSharedMemorySize, 2 * (64 + 256) * 144);
    cudaFuncSetAttribute((const void*)fus_mm, cudaFuncAttributeMaxDynamicSharedMemorySize, FUS_SMEM);

    // preprocessing (fp16 conversions)
    split_k<<<dim3(16, 128, 8), dim3(32, 8)>>>(x, xhi, 512, 0);
    wsplit_k<<<(512 * 1024 * 9 + 255) / 256, 256>>>(fus_w, wfhi, 1024, 9, (size_t)512 * 1024 * 9);
    wsplit_k<<<(64 * 512 * 9 + 255) / 256, 256>>>(box_w1, wbhi, 512, 9, (size_t)64 * 512 * 9);
    wsplit_k<<<(1536 * 512 + 255) / 256, 256>>>(qkv_w, wqhi, 512, 1, (size_t)1536 * 512);

    // box conv3x3(512->64)+GELU (1-term)
    mma_mm<9, 1, 64, 64, 256><<<dim3(128, 1), 256, 2 * (64 + 256) * 144>>>(
        wbhi, xhi, box_b1, box1, 512, 64);

    // qkv 1x1 (512->1536) (1-term)
    mma_mm<1, 0, 128, 128, 128><<<dim3(256, 12), 256, 2 * (128 + 128) * 144>>>(
        wqhi, xhi, qkv_b, qkv, 512, 1536);

    // box tail + edge net (GN stats, then fused GN+GELU+1x1)
    conv1x1_small_k<2><<<dim3(32, 16), 256>>>(box1, box_w2, box_b2, boxes, 64, 4);
    conv3x3_k<0><<<dim3(512, 1), 128>>>(boxes, 4, edge_w1, edge_b1, edge1, 64);
    gn_stats_k<<<64, 256>>>(edge1, gnst);
    edge2_k<<<dim3(8, 16), 256>>>(edge1, gnst, gn_g, gn_b, edge_w2, edge_b2, edge);

    // attention (tensor cores, 1-term)
    attn_qk_mma<<<4096, 128>>>(qkv, edge, attn);
    softmax_i_k<<<2048, 128>>>(attn);
    attn_av_mma<<<4096, 128>>>(qkv, attn, agg);

    // convert agg into ci[512:1024) of the fp16 buffer
    split_k<<<dim3(16, 128, 8), dim3(32, 8)>>>(agg, xhi, 512, 512);

    // fusion conv3x3 (1024->512), B-halo reuse + 1-term fp16
    fus_mm<<<dim3(256, 4), 256, FUS_SMEM>>>(wfhi, xhi, fus_b, y);

    // batchnorm + SiLU
    bn_stats_k<<<512, 256>>>(y, bnst);
    bn_apply_k<<<65536, 256>>>(y, bnst, bn_g, bn_b, out);
}

// round 16
// speedup vs baseline: 1.5064x; 1.0085x over previous
#include <cuda_runtime.h>
#include <cuda_fp16.h>
#include <cstdint>
#include <math.h>

#define BB 8
#define CC 512
#define PP 4096
#define NHH 8

// ---- scratch (static device globals; no allocation) ----
__device__ float g_box1[BB*64*PP];
__device__ float g_boxes[BB*4*PP];
__device__ float g_edge1[BB*64*PP];
__device__ float g_edge[BB*NHH*PP];
__device__ float g_qkv[(size_t)BB*1536*PP];
__device__ float g_attn[(size_t)BB*NHH*64*64*64];
__device__ __half g_probh[(size_t)BB*NHH*64*64*64];  // fp16 softmax probs
__device__ float g_agg[(size_t)BB*CC*PP];
__device__ float g_y[(size_t)BB*CC*PP];
__device__ float g_gnstats[BB*8*2];
__device__ float g_bnstats[CC*2];
__device__ __half g_xhi[(size_t)BB*PP*1024];   // [b][p][ci]
__device__ __half g_wfhi[512*9*1024];          // [co][tap][ci]
__device__ __half g_wbhi[64*9*512];
__device__ __half g_wqhi[1536*512];

__device__ __forceinline__ float geluf(float x) {
    return 0.5f * x * (1.0f + erff(x * 0.70710678118654752440f));
}
__device__ __forceinline__ float sigm(float x) { return 1.0f / (1.0f + __expf(-x)); }

// ---- arch-neutral tensor-core helpers (sm_80+ PTX only) ----
__device__ __forceinline__ uint32_t smem_u32(const void* p) {
    uint32_t a;
    asm("{ .reg .u64 t; cvta.to.shared.u64 t, %1; cvt.u32.u64 %0, t; }" : "=r"(a) : "l"(p));
    return a;
}
__device__ __forceinline__ void ldsm_x4(uint32_t* r, uint32_t addr) {
    asm volatile("ldmatrix.sync.aligned.m8n8.x4.shared.b16 {%0,%1,%2,%3}, [%4];"
        : "=r"(r[0]), "=r"(r[1]), "=r"(r[2]), "=r"(r[3]) : "r"(addr));
}
__device__ __forceinline__ void mma16816(float* d, const uint32_t* a, const uint32_t* b) {
    asm volatile("mma.sync.aligned.m16n8k16.row.col.f32.f16.f16.f32 "
        "{%0,%1,%2,%3}, {%4,%5,%6,%7}, {%8,%9}, {%0,%1,%2,%3};"
        : "+f"(d[0]), "+f"(d[1]), "+f"(d[2]), "+f"(d[3])
        : "r"(a[0]), "r"(a[1]), "r"(a[2]), "r"(a[3]), "r"(b[0]), "r"(b[1]));
}
__device__ __forceinline__ void cpa16(uint32_t dst, const void* src, uint32_t sz) {
    asm volatile("cp.async.cg.shared.global [%0], [%1], 16, %2;\n" :: "r"(dst), "l"(src), "r"(sz));
}
#define CP_COMMIT() asm volatile("cp.async.commit_group;\n" ::: "memory")
#define CP_WAIT1()  asm volatile("cp.async.wait_group 1;\n" ::: "memory")
#define CP_WAIT0()  asm volatile("cp.async.wait_group 0;\n" ::: "memory")

// ---- convert / transpose: NCHW fp32 -> [b][p][ci] fp16 ----
__global__ void split_k(const float* __restrict__ src, __half* __restrict__ xhi,
                        int Cn, int cibase)
{
    __shared__ float tile[32][33];
    int bz = blockIdx.z, c0 = blockIdx.x * 32, p0 = blockIdx.y * 32;
    int tx = threadIdx.x, ty = threadIdx.y;
#pragma unroll
    for (int i = 0; i < 32; i += 8)
        tile[ty + i][tx] = src[((size_t)bz * Cn + c0 + ty + i) * 4096 + p0 + tx];
    __syncthreads();
#pragma unroll
    for (int i = 0; i < 32; i += 8) {
        size_t o = ((size_t)bz * 4096 + p0 + ty + i) * 1024 + cibase + c0 + tx;
        xhi[o] = __float2half_rn(tile[tx][ty + i]);
    }
}

// OIHW fp32 -> [co][tap][ci] fp16
__global__ void wsplit_k(const float* __restrict__ w, __half* __restrict__ whi,
                         int Cin, int taps, size_t total)
{
    size_t i = (size_t)blockIdx.x * 256 + threadIdx.x;
    if (i >= total) return;
    int tap = (int)(i % taps);
    size_t t2 = i / taps;
    int ci = (int)(t2 % Cin);
    int co = (int)(t2 / Cin);
    whi[((size_t)co * taps + tap) * Cin + ci] = __float2half_rn(w[i]);
}

// ================= fusion conv3x3 (1024->512): B-halo reuse + 1-term fp16 ==========
#define FA_ST 18432
#define FB0   36864
#define FB_ST 38016
#define FUS_SMEM 112896

__device__ __forceinline__ void fus_loadA(uint32_t sb, int t,
    const __half* __restrict__ whi, int co0, int c)
{
    int cik = c / 9, tap = c - cik * 9, ci0 = cik * 64;
#pragma unroll
    for (int i = 0; i < 4; i++) {
        int idx = t + i * 256;
        int row = idx >> 3, seg = idx & 7;
        const __half* src = whi + ((size_t)(co0 + row) * 9 + tap) * 1024 + ci0 + seg * 8;
        cpa16(sb + row * 144 + seg * 16, src, 16u);
    }
}

__device__ __forceinline__ void fus_loadB(uint32_t sb, int t,
    const __half* __restrict__ xhi, int b, int h0, int cik)
{
    int ci0 = cik * 64;
    for (int idx = t; idx < 2112; idx += 256) {
        int row = idx >> 3, seg = idx & 7;
        int hrel = row / 66, wrel = row - hrel * 66;
        int h = h0 - 1 + hrel, w = wrel - 1;
        bool ok = ((unsigned)h < 64u) && ((unsigned)w < 64u);
        const __half* src = xhi
            + ((size_t)(b * 4096 + (ok ? h * 64 + w : 0))) * 1024 + ci0 + seg * 8;
        cpa16(sb + row * 144 + seg * 16, src, ok ? 16u : 0u);
    }
}

__global__ __launch_bounds__(256, 2) void fus_mm(
    const __half* __restrict__ whi, const __half* __restrict__ xhi,
    const float* __restrict__ bias, float* __restrict__ out)
{
    extern __shared__ char dynsmem[];
    const int b = blockIdx.x >> 5;
    const int pbase = (blockIdx.x & 31) * 128;
    const int h0 = pbase >> 6;
    const int co0 = blockIdx.y * 128;
    const int t = threadIdx.x, lane = t & 31, warp = t >> 5;
    const int wm = warp & 1, wn = warp >> 1;
    const uint32_t sb = smem_u32(dynsmem);

    float acc[4][4][4];
#pragma unroll
    for (int fm = 0; fm < 4; fm++)
#pragma unroll
        for (int fn = 0; fn < 4; fn++)
#pragma unroll
            for (int k = 0; k < 4; k++) acc[fm][fn][k] = 0.f;

    fus_loadB(sb + FB0, t, xhi, b, h0, 0);
    fus_loadA(sb, t, whi, co0, 0);
    CP_COMMIT();
    fus_loadA(sb + FA_ST, t, whi, co0, 1);
    CP_COMMIT();

    const int arow = wm * 64 + (lane & 15);
    const int akoff = (lane >> 4) * 16;
    const int l8 = lane & 7, grp = lane >> 3;
    const int bprel = wn * 32 + l8 + (grp >> 1) * 8;
    const int bkoff = (grp & 1) * 16;
    const int bhw = (bprel >> 6) * 66 + (bprel & 63);

    for (int c = 0; c < 144; c++) {
        if (c == 143) { CP_WAIT0(); } else { CP_WAIT1(); }
        __syncthreads();
        const int cik = c / 9, tap = c - cik * 9;
        const int tapoff = (tap / 3) * 66 + (tap % 3);
        const uint32_t Ast = sb + (c & 1) * FA_ST;
        const uint32_t Bst = sb + FB0 + (cik & 1) * FB_ST;
        const uint32_t abase = Ast + arow * 144 + akoff;
        const uint32_t bbase = Bst + (bhw + tapoff) * 144 + bkoff;
#pragma unroll
        for (int ks = 0; ks < 4; ks++) {
            const int kb = ks * 32;
            uint32_t ah[4][4];
#pragma unroll
            for (int fm = 0; fm < 4; fm++)
                ldsm_x4(ah[fm], abase + fm * 16 * 144 + kb);
            uint32_t bh[4][2];
#pragma unroll
            for (int fp = 0; fp < 2; fp++) {
                uint32_t r[4];
                ldsm_x4(r, bbase + fp * 16 * 144 + kb);
                bh[fp*2][0] = r[0]; bh[fp*2][1] = r[1];
                bh[fp*2+1][0] = r[2]; bh[fp*2+1][1] = r[3];
            }
#pragma unroll
            for (int fm = 0; fm < 4; fm++)
#pragma unroll
                for (int fn = 0; fn < 4; fn++)
                    mma16816(acc[fm][fn], ah[fm], bh[fn]);
        }
        __syncthreads();
        if (c + 2 < 144)
            fus_loadA(Ast, t, whi, co0, c + 2);
        if (tap == 0 && cik + 1 < 16)
            fus_loadB(sb + FB0 + ((cik + 1) & 1) * FB_ST, t, xhi, b, h0, cik + 1);
        CP_COMMIT();
    }

    const int r0 = lane >> 2, c0 = (lane & 3) * 2;
#pragma unroll
    for (int fm = 0; fm < 4; fm++) {
        int co = co0 + wm * 64 + fm * 16 + r0;
        float bv0 = bias[co], bv8 = bias[co + 8];
        float* op0 = out + ((size_t)b * 512 + co) * 4096 + pbase;
        float* op8 = op0 + (size_t)8 * 4096;
#pragma unroll
        for (int fn = 0; fn < 4; fn++) {
            int p = wn * 32 + fn * 8 + c0;
            *(float2*)(op0 + p) = make_float2(acc[fm][fn][0] + bv0, acc[fm][fn][1] + bv0);
            *(float2*)(op8 + p) = make_float2(acc[fm][fn][2] + bv8, acc[fm][fn][3] + bv8);
        }
    }
}

// ---- generic mma.sync implicit GEMM (qkv 1x1, box conv), 1-term fp16 ----
template<int TAPS, int COUTV, int ROWSA, int ROWSB>
__device__ __forceinline__ void mm_load(uint32_t sb, int t,
    const __half* __restrict__ whi, const __half* __restrict__ xhi,
    int co0, int WCin, int b, int pbase, int c)
{
    const int B_HI_ = ROWSA * 144;
    int cik = c / TAPS, tap = c - cik * TAPS;
    int dh = (TAPS == 9) ? tap / 3 - 1 : 0;
    int dw = (TAPS == 9) ? tap % 3 - 1 : 0;
    int ci0 = cik * 64;
#pragma unroll
    for (int i = 0; i < ROWSA / 32; i++) {
        int idx = t + i * 256;
        int row = idx >> 3, seg = idx & 7;
        int rr = (COUTV < ROWSA && row >= COUTV) ? 0 : row;
        const __half* src = whi
            + ((size_t)(co0 + rr) * TAPS + tap) * WCin + ci0 + seg * 8;
        cpa16(sb + row * 144 + seg * 16, src,
              (COUTV < ROWSA && row >= COUTV) ? 0u : 16u);
    }
#pragma unroll
    for (int i = 0; i < ROWSB / 32; i++) {
        int idx = t + i * 256;
        int row = idx >> 3, seg = idx & 7;
        int p = pbase + row;
        int ih = (p >> 6) + dh, iw = (p & 63) + dw;
        bool ok = (TAPS == 1) || (((unsigned)ih < 64u) && ((unsigned)iw < 64u));
        const __half* src = xhi
            + ((size_t)(b * 4096 + (ok ? ih * 64 + iw : 0))) * 1024 + ci0 + seg * 8;
        cpa16(sb + B_HI_ + row * 144 + seg * 16, src, ok ? 16u : 0u);
    }
}

template<int TAPS, int ACT, int COUTV, int ROWSA, int ROWSB>
__global__ __launch_bounds__(256, 2) void mma_mm(
    const __half* __restrict__ whi, const __half* __restrict__ xhi,
    const float* __restrict__ bias, float* __restrict__ out, int WCin, int Cout)
{
    extern __shared__ char dynsmem[];
    const int B_HI_ = ROWSA * 144;
    const int MSTAGE_ = (ROWSA + ROWSB) * 144;
    const int NPT = 4096 / ROWSB;
    const int b = blockIdx.x / NPT;
    const int pbase = (blockIdx.x % NPT) * ROWSB;
    const int co0 = blockIdx.y * ROWSA;
    const int t = threadIdx.x, lane = t & 31, warp = t >> 5;
    const int wm = (ROWSA == 128) ? (warp & 1) : 0;
    const int wn = (ROWSA == 128) ? (warp >> 1) : warp;
    const uint32_t sb0 = smem_u32(dynsmem);
    const int NCH = (WCin / 64) * TAPS;

    float acc[4][4][4];
#pragma unroll
    for (int fm = 0; fm < 4; fm++)
#pragma unroll
        for (int fn = 0; fn < 4; fn++)
#pragma unroll
            for (int k = 0; k < 4; k++) acc[fm][fn][k] = 0.f;

    mm_load<TAPS, COUTV, ROWSA, ROWSB>(sb0, t, whi, xhi, co0, WCin, b, pbase, 0); CP_COMMIT();
    mm_load<TAPS, COUTV, ROWSA, ROWSB>(sb0 + MSTAGE_, t, whi, xhi, co0, WCin, b, pbase, 1); CP_COMMIT();

    const int arow = wm * 64 + (lane & 15);
    const int akoff = (lane >> 4) * 16;
    const int l8 = lane & 7, grp = lane >> 3;
    const int brow = wn * 32 + l8 + (grp >> 1) * 8;
    const int bkoff = (grp & 1) * 16;

    for (int c = 0; c < NCH; c++) {
        const uint32_t sb = sb0 + (c & 1) * MSTAGE_;
        if (c == NCH - 1) { CP_WAIT0(); } else { CP_WAIT1(); }
        __syncthreads();
        const uint32_t abase = sb + arow * 144 + akoff;
        const uint32_t bbase = sb + B_HI_ + brow * 144 + bkoff;
#pragma unroll
        for (int ks = 0; ks < 4; ks++) {
            const int kb = ks * 32;
            uint32_t ah[4][4];
#pragma unroll
            for (int fm = 0; fm < 4; fm++)
                ldsm_x4(ah[fm], abase + fm * 16 * 144 + kb);
            uint32_t bh[4][2];
#pragma unroll
            for (int fp = 0; fp < 2; fp++) {
                uint32_t r[4];
                ldsm_x4(r, bbase + fp * 16 * 144 + kb);
                bh[fp*2][0] = r[0]; bh[fp*2][1] = r[1];
                bh[fp*2+1][0] = r[2]; bh[fp*2+1][1] = r[3];
            }
#pragma unroll
            for (int fm = 0; fm < 4; fm++)
#pragma unroll
                for (int fn = 0; fn < 4; fn++)
                    mma16816(acc[fm][fn], ah[fm], bh[fn]);
        }
        __syncthreads();
        if (c + 2 < NCH) {
            mm_load<TAPS, COUTV, ROWSA, ROWSB>(sb, t, whi, xhi, co0, WCin, b, pbase, c + 2);
            CP_COMMIT();
        }
    }

    const int r0 = lane >> 2, c0 = (lane & 3) * 2;
#pragma unroll
    for (int fm = 0; fm < 4; fm++) {
        int co = co0 + wm * 64 + fm * 16 + r0;
        bool v0ok = (COUTV >= ROWSA) || (co < COUTV);
        bool v8ok = (COUTV >= ROWSA) || (co + 8 < COUTV);
        float bv0 = v0ok ? bias[co] : 0.f;
        float bv8 = v8ok ? bias[co + 8] : 0.f;
        float* op0 = out + ((size_t)b * Cout + co) * 4096 + pbase;
        float* op8 = op0 + (size_t)8 * 4096;
#pragma unroll
        for (int fn = 0; fn < 4; fn++) {
            int p = wn * 32 + fn * 8 + c0;
            float a0 = acc[fm][fn][0] + bv0, a1 = acc[fm][fn][1] + bv0;
            float a2 = acc[fm][fn][2] + bv8, a3 = acc[fm][fn][3] + bv8;
            if (ACT == 1) { a0 = geluf(a0); a1 = geluf(a1); a2 = geluf(a2); a3 = geluf(a3); }
            if (v0ok) *(float2*)(op0 + p) = make_float2(a0, a1);
            if (v8ok) *(float2*)(op8 + p) = make_float2(a2, a3);
        }
    }
}

// ---- attention QK logits via mma (1-term fp16) ----
__global__ __launch_bounds__(128) void attn_qk_mma(
    const float* __restrict__ qkv, const float* __restrict__ edge, float* __restrict__ attn)
{
    int id = blockIdx.x;
    int i = id & 63, h = (id >> 6) & 7, b = id >> 9;
    const float* Q = qkv + ((size_t)(b * 1536 + h * 64 + i)) * PP;
    const float* K = qkv + ((size_t)(b * 1536 + 512 + h * 64 + i)) * PP;
    __shared__ __half sQh[64*72], sKh[64*72];
    int t = threadIdx.x, lane = t & 31, warp = t >> 5;
    int wm = warp & 1, wn = warp >> 1;
    for (int idx = t; idx < 4096; idx += 128) {
        int y = idx >> 6, c = idx & 63;
        sQh[c*72 + y] = __float2half_rn(Q[idx]);
        sKh[c*72 + y] = __float2half_rn(K[idx]);
    }
    __syncthreads();
    float acc[2][4][4];
#pragma unroll
    for (int fm = 0; fm < 2; fm++)
#pragma unroll
        for (int fn = 0; fn < 4; fn++)
#pragma unroll
            for (int k = 0; k < 4; k++) acc[fm][fn][k] = 0.f;

    const uint32_t aQh = smem_u32(sQh), aKh = smem_u32(sKh);
    const int arow = wm * 32 + (lane & 15), akoff = (lane >> 4) * 16;
    const int l8 = lane & 7, grp = lane >> 3;
    const int brow = wn * 32 + l8 + (grp >> 1) * 8, bkoff = (grp & 1) * 16;
#pragma unroll
    for (int ks = 0; ks < 4; ks++) {
        const int kb = ks * 32;
        uint32_t ah[2][4];
#pragma unroll
        for (int fm = 0; fm < 2; fm++)
            ldsm_x4(ah[fm], aQh + (arow + fm*16) * 144 + akoff + kb);
        uint32_t bh[4][2];
#pragma unroll
        for (int fp = 0; fp < 2; fp++) {
            uint32_t r[4];
            ldsm_x4(r, aKh + (brow + fp*16) * 144 + bkoff + kb);
            bh[fp*2][0] = r[0]; bh[fp*2][1] = r[1];
            bh[fp*2+1][0] = r[2]; bh[fp*2+1][1] = r[3];
        }
#pragma unroll
        for (int fm = 0; fm < 2; fm++)
#pragma unroll
            for (int fn = 0; fn < 4; fn++)
                mma16816(acc[fm][fn], ah[fm], bh[fn]);
    }
    const int r0 = lane >> 2, c0 = (lane & 3) * 2;
    float* op = attn + (size_t)id * 4096;
    const float* ep = edge + (size_t)id * 64;
#pragma unroll
    for (int fm = 0; fm < 2; fm++) {
        int w0 = wm * 32 + fm * 16 + r0;
        float e0 = ep[w0], e8 = ep[w0 + 8];
#pragma unroll
        for (int fn = 0; fn < 4; fn++) {
            int Wp = wn * 32 + fn * 8 + c0;
            op[w0*64 + Wp]       = acc[fm][fn][0] * 0.125f + e0;
            op[w0*64 + Wp + 1]   = acc[fm][fn][1] * 0.125f + e0;
            op[(w0+8)*64 + Wp]   = acc[fm][fn][2] * 0.125f + e8;
            op[(w0+8)*64 + Wp+1] = acc[fm][fn][3] * 0.125f + e8;
        }
    }
}

// ---- attention AV via mma (fp16 probs in) ----
__global__ __launch_bounds__(128) void attn_av_mma(
    const float* __restrict__ qkv, const __half* __restrict__ probs, float* __restrict__ agg)
{
    int id = blockIdx.x;
    int i = id & 63, h = (id >> 6) & 7, b = id >> 9;
    const float* V = qkv + ((size_t)(b * 1536 + 1024 + h * 64 + i)) * PP;
    const __half* A = probs + (size_t)id * 4096;
    __shared__ __half sVh[64*72], sAh[64*72];
    int t = threadIdx.x, lane = t & 31, warp = t >> 5;
    int wm = warp & 1, wn = warp >> 1;
    for (int idx = t; idx < 4096; idx += 128) {
        int r = idx >> 6, c = idx & 63;
        sVh[r*72 + c] = __float2half_rn(V[idx]);
        sAh[r*72 + c] = A[idx];
    }
    __syncthreads();
    float acc[2][4][4];
#pragma unroll
    for (int fm = 0; fm < 2; fm++)
#pragma unroll
        for (int fn = 0; fn < 4; fn++)
#pragma unroll
            for (int k = 0; k < 4; k++) acc[fm][fn][k] = 0.f;

    const uint32_t aVh = smem_u32(sVh), aAh = smem_u32(sAh);
    const int arow = wm * 32 + (lane & 15), akoff = (lane >> 4) * 16;
    const int l8 = lane & 7, grp = lane >> 3;
    const int brow = wn * 32 + l8 + (grp >> 1) * 8, bkoff = (grp & 1) * 16;
#pragma unroll
    for (int ks = 0; ks < 4; ks++) {
        const int kb = ks * 32;
        uint32_t ah[2][4];
#pragma unroll
        for (int fm = 0; fm < 2; fm++)
            ldsm_x4(ah[fm], aVh + (arow + fm*16) * 144 + akoff + kb);
        uint32_t bh[4][2];
#pragma unroll
        for (int fp = 0; fp < 2; fp++) {
            uint32_t r[4];
            ldsm_x4(r, aAh + (brow + fp*16) * 144 + bkoff + kb);
            bh[fp*2][0] = r[0]; bh[fp*2][1] = r[1];
            bh[fp*2+1][0] = r[2]; bh[fp*2+1][1] = r[3];
        }
#pragma unroll
        for (int fm = 0; fm < 2; fm++)
#pragma unroll
            for (int fn = 0; fn < 4; fn++)
                mma16816(acc[fm][fn], ah[fm], bh[fn]);
    }
    const int r0 = lane >> 2, c0 = (lane & 3) * 2;
    float* op = agg + ((size_t)(b * 512 + h * 64 + i)) * PP;
#pragma unroll
    for (int fm = 0; fm < 2; fm++) {
        int d0 = wm * 32 + fm * 16 + r0;
#pragma unroll
        for (int fn = 0; fn < 4; fn++) {
            int w = wn * 32 + fn * 8 + c0;
            op[d0*64 + w]       = acc[fm][fn][0];
            op[d0*64 + w + 1]   = acc[fm][fn][1];
            op[(d0+8)*64 + w]   = acc[fm][fn][2];
            op[(d0+8)*64 + w+1] = acc[fm][fn][3];
        }
    }
}

// ---- FFMA 3x3 conv (edge net: Cin=4 -> 64 only) ----
#define CI_CHUNK 8
template<int ACT>
__global__ __launch_bounds__(128) void conv3x3_k(
    const float* __restrict__ in1, int Cin,
    const float* __restrict__ wgt, const float* __restrict__ bias,
    float* __restrict__ out, int Cout)
{
    const int bh = blockIdx.x, b = bh >> 6, h = bh & 63;
    const int co0 = blockIdx.y * 64;
    const int t = threadIdx.x, tx = t & 7, ty = t >> 3;
    __shared__ float sIn[CI_CHUNK][3][66];
    __shared__ float sW[64][CI_CHUNK * 9];
    float acc[4][8];
#pragma unroll
    for (int a = 0; a < 4; a++)
#pragma unroll
        for (int j = 0; j < 8; j++) acc[a][j] = 0.f;

    for (int cb = 0; cb < Cin; cb += CI_CHUNK) {
        __syncthreads();
        for (int idx = t; idx < CI_CHUNK * 3 * 66; idx += 128) {
            int ci = idx / 198, rem = idx - ci * 198, r = rem / 66, col = rem - r * 66;
            int cg = cb + ci;
            float v = 0.f;
            int gh = h - 1 + r, gw = col - 1;
            if (cg < Cin && (unsigned)gh < 64u && (unsigned)gw < 64u)
                v = in1[((size_t)(b * Cin + cg)) * PP + gh * 64 + gw];
            sIn[ci][r][col] = v;
        }
        for (int idx = t; idx < 64 * CI_CHUNK * 9; idx += 128) {
            int co = idx / (CI_CHUNK * 9), rem = idx - co * (CI_CHUNK * 9);
            int ci = rem / 9, kk = rem - ci * 9, cg = cb + ci;
            sW[co][ci * 9 + kk] = (cg < Cin) ? wgt[((size_t)(co0 + co) * Cin + cg) * 9 + kk] : 0.f;
        }
        __syncthreads();
#pragma unroll 2
        for (int ci = 0; ci < CI_CHUNK; ci++) {
#pragma unroll
            for (int r = 0; r < 3; r++) {
                float iv[10];
#pragma unroll
                for (int j = 0; j < 10; j++) iv[j] = sIn[ci][r][tx * 8 + j];
#pragma unroll
                for (int cj = 0; cj < 4; cj++) {
                    float w0 = sW[ty * 4 + cj][ci * 9 + r * 3 + 0];
                    float w1 = sW[ty * 4 + cj][ci * 9 + r * 3 + 1];
                    float w2 = sW[ty * 4 + cj][ci * 9 + r * 3 + 2];
#pragma unroll
                    for (int wj = 0; wj < 8; wj++) {
                        acc[cj][wj] = fmaf(w0, iv[wj + 0], acc[cj][wj]);
                        acc[cj][wj] = fmaf(w1, iv[wj + 1], acc[cj][wj]);
                        acc[cj][wj] = fmaf(w2, iv[wj + 2], acc[cj][wj]);
                    }
                }
            }
        }
    }
#pragma unroll
    for (int cj = 0; cj < 4; cj++) {
        int co = co0 + ty * 4 + cj;
        float bv = bias[co];
#pragma unroll
        for (int wj = 0; wj < 8; wj++) {
            float v = acc[cj][wj] + bv;
            if (ACT == 1) v = geluf(v);
            out[(((size_t)b * Cout + co) * 64 + h) * 64 + tx * 8 + wj] = v;
        }
    }
}

template<int ACT>
__global__ void conv1x1_small_k(const float* __restrict__ in, const float* __restrict__ wgt,
                                const float* __restrict__ bias, float* __restrict__ out,
                                int Cin, int Cout)
{
    int bc = blockIdx.x, b = bc / Cout, co = bc - b * Cout;
    int p = blockIdx.y * 256 + threadIdx.x;
    float acc = bias[co];
    const float* ip = in + (size_t)b * Cin * PP + p;
    const float* wp = wgt + (size_t)co * Cin;
    for (int ci = 0; ci < Cin; ci++)
        acc = fmaf(wp[ci], ip[(size_t)ci * PP], acc);
    if (ACT == 2) acc = sigm(acc);
    out[((size_t)b * Cout + co) * PP + p] = acc;
}

// ---- GroupNorm stats ----
__global__ void gn_stats_k(const float* __restrict__ x, float* __restrict__ stats)
{
    int bg = blockIdx.x, b = bg >> 3, g = bg & 7;
    const float* p = x + ((size_t)b * 64 + g * 8) * PP;
    float s = 0.f, s2 = 0.f;
    for (int i = threadIdx.x; i < 8 * PP; i += 256) {
        float v = p[i]; s += v; s2 += v * v;
    }
    __shared__ float rs[8], rs2[8];
#pragma unroll
    for (int o = 16; o > 0; o >>= 1) {
        s += __shfl_down_sync(0xffffffffu, s, o);
        s2 += __shfl_down_sync(0xffffffffu, s2, o);
    }
    int w = threadIdx.x >> 5, l = threadIdx.x & 31;
    if (l == 0) { rs[w] = s; rs2[w] = s2; }
    __syncthreads();
    if (w == 0) {
        s = (l < 8) ? rs[l] : 0.f; s2 = (l < 8) ? rs2[l] : 0.f;
#pragma unroll
        for (int o = 4; o > 0; o >>= 1) {
            s += __shfl_down_sync(0xffffffffu, s, o);
            s2 += __shfl_down_sync(0xffffffffu, s2, o);
        }
        if (l == 0) {
            float m = s / 32768.f;
            stats[bg * 2] = m;
            stats[bg * 2 + 1] = s2 / 32768.f - m * m;
        }
    }
}

// ---- fused GN + GELU + 1x1 conv (64->8): edge net tail ----
__global__ __launch_bounds__(256) void edge2_k(
    const float* __restrict__ edge1, const float* __restrict__ stats,
    const float* __restrict__ gamma, const float* __restrict__ beta,
    const float* __restrict__ w2, const float* __restrict__ b2,
    float* __restrict__ edge)
{
    int b = blockIdx.x;
    int p = blockIdx.y * 256 + threadIdx.x;
    __shared__ float sm[8], srs[8], sg[64], sbt[64], sw[8][64], sb2[8];
    int t = threadIdx.x;
    if (t < 8) {
        sm[t] = stats[(b * 8 + t) * 2];
        srs[t] = rsqrtf(stats[(b * 8 + t) * 2 + 1] + 1e-5f);
        sb2[t] = b2[t];
    }
    if (t < 64) { sg[t] = gamma[t]; sbt[t] = beta[t]; }
    for (int i = t; i < 512; i += 256) sw[i >> 6][i & 63] = w2[i];
    __syncthreads();

    float acc[8];
#pragma unroll
    for (int co = 0; co < 8; co++) acc[co] = sb2[co];
    const float* ip = edge1 + (size_t)b * 64 * PP + p;
    for (int ci = 0; ci < 64; ci++) {
        int g = ci >> 3;
        float xn = geluf((ip[(size_t)ci * PP] - sm[g]) * srs[g] * sg[ci] + sbt[ci]);
#pragma unroll
        for (int co = 0; co < 8; co++)
            acc[co] = fmaf(sw[co][ci], xn, acc[co]);
    }
#pragma unroll
    for (int co = 0; co < 8; co++)
        edge[((size_t)b * 8 + co) * PP + p] = acc[co];
}

// ---- softmax over i (fp32 logits in, fp16 probs out) ----
__global__ __launch_bounds__(128) void softmax_i_k(const float* __restrict__ attn,
                                                   __half* __restrict__ probs)
{
    int n = blockIdx.x * 128 + threadIdx.x;
    int bh = n >> 12, ww = n & 4095;
    const float* p = attn + (size_t)bh * 262144 + ww;
    __half* q = probs + (size_t)bh * 262144 + ww;
    float x[64], mx = -1e30f;
#pragma unroll
    for (int i = 0; i < 64; i++) { x[i] = p[(size_t)i * 4096]; mx = fmaxf(mx, x[i]); }
    float s = 0.f;
#pragma unroll
    for (int i = 0; i < 64; i++) { x[i] = __expf(x[i] - mx); s += x[i]; }
    float inv = 1.f / s;
#pragma unroll
    for (int i = 0; i < 64; i++) q[(size_t)i * 4096] = __float2half_rn(x[i] * inv);
}

// ---- BatchNorm ----
__global__ void bn_stats_k(const float* __restrict__ y, float* __restrict__ stats)
{
    int c = blockIdx.x;
    float s = 0.f, s2 = 0.f;
    for (int n = threadIdx.x; n < 32768; n += 256) {
        int b = n >> 12, p = n & 4095;
        float v = y[((size_t)b * CC + c) * PP + p];
        s += v; s2 += v * v;
    }
    __shared__ float rs[8], rs2[8];
#pragma unroll
    for (int o = 16; o > 0; o >>= 1) {
        s += __shfl_down_sync(0xffffffffu, s, o);
        s2 += __shfl_down_sync(0xffffffffu, s2, o);
    }
    int w = threadIdx.x >> 5, l = threadIdx.x & 31;
    if (l == 0) { rs[w] = s; rs2[w] = s2; }
    __syncthreads();
    if (w == 0) {
        s = (l < 8) ? rs[l] : 0.f; s2 = (l < 8) ? rs2[l] : 0.f;
#pragma unroll
        for (int o = 4; o > 0; o >>= 1) {
            s += __shfl_down_sync(0xffffffffu, s, o);
            s2 += __shfl_down_sync(0xffffffffu, s2, o);
        }
        if (l == 0) {
            float m = s / 32768.f;
            stats[c * 2] = m;
            stats[c * 2 + 1] = s2 / 32768.f - m * m;
        }
    }
}

__global__ void bn_apply_k(const float* __restrict__ y, const float* __restrict__ stats,
                           const float* __restrict__ g, const float* __restrict__ bt,
                           float* __restrict__ out)
{
    size_t idx = (size_t)blockIdx.x * 256 + threadIdx.x;
    int c = (int)((idx >> 12) & 511);
    float m = stats[c * 2], v = stats[c * 2 + 1];
    float yn = (y[idx] - m) * rsqrtf(v + 1e-5f) * g[c] + bt[c];
    out[idx] = yn * (1.f / (1.f + __expf(-yn)));
}

// ---- launch ----
extern "C" void kernel_launch(void* const* d_in, const int* in_sizes, int n_in,
                              void* d_out, int out_size)
{
    const float* x       = (const float*)d_in[0];
    const float* box_w1  = (const float*)d_in[1];
    const float* box_b1  = (const float*)d_in[2];
    const float* box_w2  = (const float*)d_in[3];
    const float* box_b2  = (const float*)d_in[4];
    const float* edge_w1 = (const float*)d_in[5];
    const float* edge_b1 = (const float*)d_in[6];
    const float* gn_g    = (const float*)d_in[7];
    const float* gn_b    = (const float*)d_in[8];
    const float* edge_w2 = (const float*)d_in[9];
    const float* edge_b2 = (const float*)d_in[10];
    const float* qkv_w   = (const float*)d_in[11];
    const float* qkv_b   = (const float*)d_in[12];
    const float* fus_w   = (const float*)d_in[13];
    const float* fus_b   = (const float*)d_in[14];
    const float* bn_g    = (const float*)d_in[15];
    const float* bn_b    = (const float*)d_in[16];
    float* out = (float*)d_out;

    float *box1, *boxes, *edge1, *edge, *qkv, *attn, *agg, *y, *gnst, *bnst;
    __half *xhi, *wfhi, *wbhi, *wqhi, *probh;
    cudaGetSymbolAddress((void**)&box1,  g_box1);
    cudaGetSymbolAddress((void**)&boxes, g_boxes);
    cudaGetSymbolAddress((void**)&edge1, g_edge1);
    cudaGetSymbolAddress((void**)&edge,  g_edge);
    cudaGetSymbolAddress((void**)&qkv,   g_qkv);
    cudaGetSymbolAddress((void**)&attn,  g_attn);
    cudaGetSymbolAddress((void**)&agg,   g_agg);
    cudaGetSymbolAddress((void**)&y,     g_y);
    cudaGetSymbolAddress((void**)&gnst,  g_gnstats);
    cudaGetSymbolAddress((void**)&bnst,  g_bnstats);
    cudaGetSymbolAddress((void**)&xhi,   g_xhi);
    cudaGetSymbolAddress((void**)&wfhi,  g_wfhi);
    cudaGetSymbolAddress((void**)&wbhi,  g_wbhi);
    cudaGetSymbolAddress((void**)&wqhi,  g_wqhi);
    cudaGetSymbolAddress((void**)&probh, g_probh);

    cudaFuncSetAttribute((const void*)mma_mm<1, 0, 128, 128, 128>, cudaFuncAttributeMaxDynamicSharedMemorySize, 2 * (128 + 128) * 144);
    cudaFuncSetAttribute((const void*)mma_mm<9, 1, 64, 64, 256>,   cudaFuncAttributeMaxDynamicSharedMemorySize, 2 * (64 + 256) * 144);
    cudaFuncSetAttribute((const void*)fus_mm, cudaFuncAttributeMaxDynamicSharedMemorySize, FUS_SMEM);

    // 1-3: preprocessing needed for qkv/box
    split_k<<<dim3(16, 128, 8), dim3(32, 8)>>>(x, xhi, 512, 0);
    wsplit_k<<<(1536 * 512 + 255) / 256, 256>>>(qkv_w, wqhi, 512, 1, (size_t)1536 * 512);
    wsplit_k<<<(64 * 512 * 9 + 255) / 256, 256>>>(box_w1, wbhi, 512, 9, (size_t)64 * 512 * 9);

    // 4: qkv 1x1 (512->1536)  [profiled by ncu next round]
    mma_mm<1, 0, 128, 128, 128><<<dim3(256, 12), 256, 2 * (128 + 128) * 144>>>(
        wqhi, xhi, qkv_b, qkv, 512, 1536);

    // 5: box conv3x3(512->64)+GELU
    mma_mm<9, 1, 64, 64, 256><<<dim3(128, 1), 256, 2 * (64 + 256) * 144>>>(
        wbhi, xhi, box_b1, box1, 512, 64);

    // box tail + edge net
    conv1x1_small_k<2><<<dim3(32, 16), 256>>>(box1, box_w2, box_b2, boxes, 64, 4);
    conv3x3_k<0><<<dim3(512, 1), 128>>>(boxes, 4, edge_w1, edge_b1, edge1, 64);
    gn_stats_k<<<64, 256>>>(edge1, gnst);
    edge2_k<<<dim3(8, 16), 256>>>(edge1, gnst, gn_g, gn_b, edge_w2, edge_b2, edge);

    // attention (tensor cores; softmax emits fp16 probs — bit-identical to prior rounding)
    attn_qk_mma<<<4096, 128>>>(qkv, edge, attn);
    softmax_i_k<<<2048, 128>>>(attn, probh);
    attn_av_mma<<<4096, 128>>>(qkv, probh, agg);

    // convert agg into ci[512:1024) of the fp16 buffer; fusion weights
    split_k<<<dim3(16, 128, 8), dim3(32, 8)>>>(agg, xhi, 512, 512);
    wsplit_k<<<(512 * 1024 * 9 + 255) / 256, 256>>>(fus_w, wfhi, 1024, 9, (size_t)512 * 1024 * 9);

    // fusion conv3x3 (1024->512), B-halo reuse + 1-term fp16
    fus_mm<<<dim3(256, 4), 256, FUS_SMEM>>>(wfhi, xhi, fus_b, y);

    // batchnorm + SiLU
    bn_stats_k<<<512, 256>>>(y, bnst);
    bn_apply_k<<<65536, 256>>>(y, bnst, bn_g, bn_b, out);
}